// round 11
// baseline (speedup 1.0000x reference)
#include <cuda_runtime.h>
#include <cuda_bf16.h>
#include <cstdint>

// ---------------------------------------------------------------------------
// Problem constants
// ---------------------------------------------------------------------------
#define BB 2
#define LL 2048
#define DD 1024
#define HH 16
#define HD 64
#define BL (BB*LL)           // 4096
#define EPS 1e-6f

// ---------------------------------------------------------------------------
// Scratch
// ---------------------------------------------------------------------------
__device__ float g_xn [BL*DD];
__device__ float g_cp [BL*3*DD];
__device__ float g_xm [BL*DD];             // modulated x, tf32-rounded
__device__ float g_qkv[BL*3*DD];
__device__ float g_q  [BL*DD];             // [B,H,L,HD], x0.125, tf32-rounded
__device__ float g_kT [BL*DD];             // [B,H,HD,L], tf32-rounded
__device__ float g_v  [BL*DD];             // [B,H,L,HD], tf32-rounded
__device__ float g_att[BL*DD];             // attn out [B,L,D], tf32-rounded
__device__ float g_cr [BL*DD];             // cond, tf32-rounded
__device__ float g_wc [DD*3*DD];           // W_cond, tf32-rounded
__device__ float g_wq [DD*3*DD];           // W_qkv, tf32-rounded
__device__ float g_wo [DD*DD];             // W_out, tf32-rounded

// ---------------------------------------------------------------------------
// helpers
// ---------------------------------------------------------------------------
__device__ __forceinline__ float to_tf32(float x) {
    uint32_t r;
    asm("cvt.rna.tf32.f32 %0, %1;" : "=r"(r) : "f"(x));
    return __uint_as_float(r);
}

__device__ __forceinline__ void mma_tf32(float acc[4],
                                         uint32_t a0, uint32_t a1, uint32_t a2, uint32_t a3,
                                         uint32_t b0, uint32_t b1) {
    asm volatile(
        "mma.sync.aligned.m16n8k8.row.col.f32.tf32.tf32.f32 "
        "{%0,%1,%2,%3}, {%4,%5,%6,%7}, {%8,%9}, {%0,%1,%2,%3};\n"
        : "+f"(acc[0]), "+f"(acc[1]), "+f"(acc[2]), "+f"(acc[3])
        : "r"(a0), "r"(a1), "r"(a2), "r"(a3), "r"(b0), "r"(b1));
}

__device__ __forceinline__ uint32_t smem_u32(const void* p) {
    return (uint32_t)__cvta_generic_to_shared(p);
}

#define CP_ASYNC16(dst_u32, src_ptr) \
    asm volatile("cp.async.cg.shared.global [%0], [%1], 16;\n" \
                 :: "r"(dst_u32), "l"(src_ptr))
#define CP_COMMIT() asm volatile("cp.async.commit_group;\n")
#define CP_WAIT1()  asm volatile("cp.async.wait_group 1;\n")

// GEMM smem sizing (BM=128, BN=128, BK=16, 3 stages) — dynamic smem
#define G_BK    16
#define G_NST   3
#define G_ASTR  (G_BK + 4)          // 20
#define G_BSTR  (128 + 8)           // 136
#define G_ASZ   (128 * G_ASTR)      // 2560 floats
#define G_BSZ   (G_BK * G_BSTR)     // 2176 floats
#define MMA_SMEM_BYTES ((G_NST * (G_ASZ + G_BSZ)) * (int)sizeof(float))  // 56832

// ---------------------------------------------------------------------------
// tf32 pre-round: out[i] = rna(in[i]).
// ---------------------------------------------------------------------------
__global__ void round_kernel(const float* __restrict__ in,
                             float* __restrict__ out)
{
    const int i = blockIdx.x * blockDim.x + threadIdx.x;
    float4 v = ((const float4*)in)[i];
    v.x = to_tf32(v.x); v.y = to_tf32(v.y);
    v.z = to_tf32(v.z); v.w = to_tf32(v.w);
    ((float4*)out)[i] = v;
}

// ---------------------------------------------------------------------------
// Batched tf32 tensor-core GEMM (NN), 3-stage cp.async pipeline,
// ONE __syncthreads per K-tile, zero hot-loop cvts (operands pre-rounded).
// ---------------------------------------------------------------------------
template<int BM, int BN, bool EPI>
__global__ void __launch_bounds__(256)
mma_gemm(const float* __restrict__ A, const float* __restrict__ Bg,
         float* __restrict__ C,
         int K, int lda, int ldb, int ldc,
         long sA, long sB, int zmod, long sC_hi, long sC_lo,
         const float* __restrict__ Rres, const float* __restrict__ Gg)
{
    constexpr int BK = G_BK;
    constexpr int NST = G_NST;
    constexpr int WM = BM / 2;
    constexpr int WN = BN / 4;
    constexpr int MA = WM / 16;
    constexpr int NA = WN / 8;
    constexpr int ASTR = G_ASTR;
    constexpr int BSTR = BN + 8;
    constexpr int ASZ = BM * ASTR;
    constexpr int BSZ = BK * BSTR;

    extern __shared__ float gsm[];
    float* As = gsm;
    float* Bs = gsm + NST * ASZ;

    const int z = blockIdx.z;
    A += (long)z * sA;
    Bg += (long)z * sB;
    C += (long)(z / zmod) * sC_hi + (long)(z % zmod) * sC_lo;

    const int bm = blockIdx.y * BM;
    const int bn = blockIdx.x * BN;
    const int tid = threadIdx.x;
    const int lane = tid & 31;
    const int warp = tid >> 5;
    const int wm = warp >> 2;
    const int wn = warp & 3;
    const int g  = lane >> 2;
    const int tg = lane & 3;

    constexpr int A_IT = BM * BK / 1024;          // 2
    constexpr int A_RSTEP = 1024 / BK;            // 64
    const int arow = tid / (BK / 4);
    const int acol = (tid % (BK / 4)) * 4;
    constexpr int B_IT = BK * BN / 1024;          // 2
    constexpr int B_RSTEP = 1024 / BN;            // 8
    const int brow = tid / (BN / 4);
    const int bcol = (tid % (BN / 4)) * 4;

    float acc[MA][NA][4];
#pragma unroll
    for (int i = 0; i < MA; i++)
#pragma unroll
        for (int j = 0; j < NA; j++)
#pragma unroll
            for (int c = 0; c < 4; c++) acc[i][j][c] = 0.f;

    const int nk = K / BK;

#pragma unroll
    for (int s = 0; s < NST - 1; s++) {
        if (s < nk) {
            float* dA = As + s * ASZ;
            float* dB = Bs + s * BSZ;
#pragma unroll
            for (int i = 0; i < A_IT; i++)
                CP_ASYNC16(smem_u32(&dA[(arow + i * A_RSTEP) * ASTR + acol]),
                           &A[(long)(bm + arow + i * A_RSTEP) * lda + s * BK + acol]);
#pragma unroll
            for (int i = 0; i < B_IT; i++)
                CP_ASYNC16(smem_u32(&dB[(brow + i * B_RSTEP) * BSTR + bcol]),
                           &Bg[(long)(s * BK + brow + i * B_RSTEP) * ldb + bn + bcol]);
        }
        CP_COMMIT();
    }

    for (int it = 0; it < nk; it++) {
        CP_WAIT1();
        __syncthreads();

        const int t = it + NST - 1;
        if (t < nk) {
            const int fb = t % NST;
            float* dA = As + fb * ASZ;
            float* dB = Bs + fb * BSZ;
#pragma unroll
            for (int i = 0; i < A_IT; i++)
                CP_ASYNC16(smem_u32(&dA[(arow + i * A_RSTEP) * ASTR + acol]),
                           &A[(long)(bm + arow + i * A_RSTEP) * lda + t * BK + acol]);
#pragma unroll
            for (int i = 0; i < B_IT; i++)
                CP_ASYNC16(smem_u32(&dB[(brow + i * B_RSTEP) * BSTR + bcol]),
                           &Bg[(long)(t * BK + brow + i * B_RSTEP) * ldb + bn + bcol]);
        }
        CP_COMMIT();

        const int buf = it % NST;
        const float* cA = As + buf * ASZ;
        const float* cB = Bs + buf * BSZ;

#pragma unroll
        for (int ks = 0; ks < 2; ks++) {
            uint32_t af[MA][4], bf[NA][2];
#pragma unroll
            for (int i = 0; i < MA; i++) {
                const int r0 = (wm * WM + i * 16 + g) * ASTR + ks * 8 + tg;
                const int r1 = r0 + 8 * ASTR;
                af[i][0] = __float_as_uint(cA[r0]);
                af[i][1] = __float_as_uint(cA[r1]);
                af[i][2] = __float_as_uint(cA[r0 + 4]);
                af[i][3] = __float_as_uint(cA[r1 + 4]);
            }
#pragma unroll
            for (int j = 0; j < NA; j++) {
                const int c0 = (ks * 8 + tg) * BSTR + wn * WN + j * 8 + g;
                bf[j][0] = __float_as_uint(cB[c0]);
                bf[j][1] = __float_as_uint(cB[c0 + 4 * BSTR]);
            }
#pragma unroll
            for (int i = 0; i < MA; i++)
#pragma unroll
                for (int j = 0; j < NA; j++)
                    mma_tf32(acc[i][j], af[i][0], af[i][1], af[i][2], af[i][3],
                             bf[j][0], bf[j][1]);
        }
    }

#pragma unroll
    for (int i = 0; i < MA; i++) {
        const int r0 = bm + wm * WM + i * 16 + g;
#pragma unroll
        for (int j = 0; j < NA; j++) {
            const int c = bn + wn * WN + j * 8 + tg * 2;
            float2 v0 = make_float2(acc[i][j][0], acc[i][j][1]);
            float2 v1 = make_float2(acc[i][j][2], acc[i][j][3]);
            if (EPI) {
                v0.x += Rres[(long)r0 * DD + c]     + Gg[(long)r0 * 3 * DD + 3 * c + 2];
                v0.y += Rres[(long)r0 * DD + c + 1] + Gg[(long)r0 * 3 * DD + 3 * (c + 1) + 2];
                v1.x += Rres[(long)(r0 + 8) * DD + c]     + Gg[(long)(r0 + 8) * 3 * DD + 3 * c + 2];
                v1.y += Rres[(long)(r0 + 8) * DD + c + 1] + Gg[(long)(r0 + 8) * 3 * DD + 3 * (c + 1) + 2];
            }
            *reinterpret_cast<float2*>(&C[(long)r0 * ldc + c]) = v0;
            *reinterpret_cast<float2*>(&C[(long)(r0 + 8) * ldc + c]) = v1;
        }
    }
}

// ---------------------------------------------------------------------------
// Flash attention — fragment-major smem layouts.
//   A-blocks (Q, P): per (warp, ks) a 132-float block; thread's 4 frag regs
//   contiguous -> one LDS.128.  B-blocks (K, V): per (ks, j) a 66-float
//   block; thread's 2 frag regs contiguous -> one LDS.64.
//   q/kT/v arrive pre-rounded to tf32 (rope) -> no cvt in fills.
// ---------------------------------------------------------------------------
#define FQF  0
#define FQSZ (8*8*132)            // 8448 floats
#define FKF  FQSZ                 // 8448
#define FKSZ (8*8*66)             // 4224
#define FVF  (FKF + FKSZ)         // 12672
#define FPF  (FVF + FKSZ)         // 16896
#define F_TOT (FPF + FQSZ)        // 25344 floats = 101376 B

__global__ void __launch_bounds__(256)
flash_kernel(const float* __restrict__ q, const float* __restrict__ kT,
             const float* __restrict__ v, float* __restrict__ att)
{
    extern __shared__ float sm[];

    const int bh = blockIdx.y;
    const int b  = bh >> 4;
    const int h  = bh & (HH - 1);
    const int m0 = blockIdx.x * 128;
    const int tid = threadIdx.x;
    const int lane = tid & 31;
    const int warp = tid >> 5;
    const int g  = lane >> 2;
    const int tg = lane & 3;

    // ---- fill Q fragments (once): element (m,k) -> A-frag slot ----
    const float* qbase = q + ((long)bh * LL + m0) * HD;
    for (int i = tid; i < 128 * 16; i += 256) {
        const int m = i >> 4, k4 = (i & 15) * 4;
        float4 t = *reinterpret_cast<const float4*>(&qbase[(long)m * HD + k4]);
        const int w = m >> 4, mr = m & 15;
        const int gg = mr & 7, rb = mr >> 3;
        const int ks = k4 >> 3;
        const int half = (k4 & 4) ? 2 : 0;
        float* d = &sm[FQF + (w * 8 + ks) * 132 + gg * 16 + half + rb];
        d[0] = t.x; d[4] = t.y; d[8] = t.z; d[12] = t.w;   // tgc = 0..3
    }

    float accO[8][4];
#pragma unroll
    for (int j = 0; j < 8; j++)
#pragma unroll
        for (int c = 0; c < 4; c++) accO[j][c] = 0.f;
    float mrow0 = -1e30f, mrow1 = -1e30f, lrow0 = 0.f, lrow1 = 0.f;

    const float* kbase = kT + (long)bh * HD * LL;
    const float* vbase = v + (long)bh * LL * HD;
    const int qoff = FQF + warp * 8 * 132 + lane * 4;
    const int poff = FPF + warp * 8 * 132 + lane * 4;
    const int pwbase = FPF + warp * 8 * 132;

    for (int j0 = 0; j0 < LL; j0 += 64) {
        __syncthreads();
        // ---- fill K fragments: B[k][n] = kT[hd=k][l=j0+n] ----
        for (int i = tid; i < 64 * 16; i += 256) {
            const int k = i >> 4, n4 = (i & 15) * 4;
            float4 t = *reinterpret_cast<const float4*>(
                &kbase[(long)k * LL + j0 + n4]);
            const int ks = k >> 3, u = k & 7;
            const int tgc = u & 3, c = u >> 2;
            const int j = n4 >> 3, gb = n4 & 7;
            float* d = &sm[FKF + (ks * 8 + j) * 66 + (gb * 4 + tgc) * 2 + c];
            d[0] = t.x; d[8] = t.y; d[16] = t.z; d[24] = t.w;  // g = gb+0..3
        }
        // ---- fill V fragments: B[k][n] = v[l=j0+k][hd=n] ----
        for (int i = tid; i < 64 * 16; i += 256) {
            const int k = i >> 4, n4 = (i & 15) * 4;
            float4 t = *reinterpret_cast<const float4*>(
                &vbase[(long)(j0 + k) * HD + n4]);
            const int ks = k >> 3, u = k & 7;
            const int tgc = u & 3, c = u >> 2;
            const int j = n4 >> 3, gb = n4 & 7;
            float* d = &sm[FVF + (ks * 8 + j) * 66 + (gb * 4 + tgc) * 2 + c];
            d[0] = t.x; d[8] = t.y; d[16] = t.z; d[24] = t.w;
        }
        __syncthreads();

        // ---- S = Q @ K^T (16x64 per warp) ----
        float s[8][4];
#pragma unroll
        for (int j = 0; j < 8; j++)
#pragma unroll
            for (int c = 0; c < 4; c++) s[j][c] = 0.f;
#pragma unroll
        for (int ks = 0; ks < 8; ks++) {
            float4 a = *reinterpret_cast<const float4*>(&sm[qoff + ks * 132]);
            const uint32_t a0 = __float_as_uint(a.x);
            const uint32_t a1 = __float_as_uint(a.y);
            const uint32_t a2 = __float_as_uint(a.z);
            const uint32_t a3 = __float_as_uint(a.w);
#pragma unroll
            for (int j = 0; j < 8; j++) {
                float2 bb = *reinterpret_cast<const float2*>(
                    &sm[FKF + (ks * 8 + j) * 66 + lane * 2]);
                mma_tf32(s[j], a0, a1, a2, a3,
                         __float_as_uint(bb.x), __float_as_uint(bb.y));
            }
        }

        // ---- online softmax (rows g / g+8 of warp tile; quad reduce) ----
        float mx0 = -1e30f, mx1 = -1e30f;
#pragma unroll
        for (int j = 0; j < 8; j++) {
            mx0 = fmaxf(mx0, fmaxf(s[j][0], s[j][1]));
            mx1 = fmaxf(mx1, fmaxf(s[j][2], s[j][3]));
        }
        mx0 = fmaxf(mx0, __shfl_xor_sync(~0u, mx0, 1));
        mx0 = fmaxf(mx0, __shfl_xor_sync(~0u, mx0, 2));
        mx1 = fmaxf(mx1, __shfl_xor_sync(~0u, mx1, 1));
        mx1 = fmaxf(mx1, __shfl_xor_sync(~0u, mx1, 2));

        const float mn0 = fmaxf(mrow0, mx0);
        const float mn1 = fmaxf(mrow1, mx1);
        const float al0 = __expf(mrow0 - mn0);
        const float al1 = __expf(mrow1 - mn1);
        mrow0 = mn0; mrow1 = mn1;

        float ps0 = 0.f, ps1 = 0.f;
#pragma unroll
        for (int j = 0; j < 8; j++) {
            s[j][0] = __expf(s[j][0] - mn0);
            s[j][1] = __expf(s[j][1] - mn0);
            s[j][2] = __expf(s[j][2] - mn1);
            s[j][3] = __expf(s[j][3] - mn1);
            ps0 += s[j][0] + s[j][1];
            ps1 += s[j][2] + s[j][3];
        }
        ps0 += __shfl_xor_sync(~0u, ps0, 1);
        ps0 += __shfl_xor_sync(~0u, ps0, 2);
        ps1 += __shfl_xor_sync(~0u, ps1, 1);
        ps1 += __shfl_xor_sync(~0u, ps1, 2);
        lrow0 = lrow0 * al0 + ps0;
        lrow1 = lrow1 * al1 + ps1;

#pragma unroll
        for (int j = 0; j < 8; j++) {
            accO[j][0] *= al0; accO[j][1] *= al0;
            accO[j][2] *= al1; accO[j][3] *= al1;
        }

        // ---- store P into fragment layout (per-warp-private block) ----
        {
            const int u0 = tg * 2, u1 = u0 + 1;
            const int o0 = g * 16 + (u0 & 3) * 4 + ((u0 >> 2) << 1);
            const int o1 = g * 16 + (u1 & 3) * 4 + ((u1 >> 2) << 1);
#pragma unroll
            for (int j = 0; j < 8; j++) {
                float* pb = &sm[pwbase + j * 132];
                pb[o0]     = to_tf32(s[j][0]);
                pb[o0 + 1] = to_tf32(s[j][2]);
                pb[o1]     = to_tf32(s[j][1]);
                pb[o1 + 1] = to_tf32(s[j][3]);
            }
        }
        __syncwarp();

        // ---- O += P @ V ----
#pragma unroll
        for (int ks = 0; ks < 8; ks++) {
            float4 a = *reinterpret_cast<const float4*>(&sm[poff + ks * 132]);
            const uint32_t a0 = __float_as_uint(a.x);
            const uint32_t a1 = __float_as_uint(a.y);
            const uint32_t a2 = __float_as_uint(a.z);
            const uint32_t a3 = __float_as_uint(a.w);
#pragma unroll
            for (int j = 0; j < 8; j++) {
                float2 bb = *reinterpret_cast<const float2*>(
                    &sm[FVF + (ks * 8 + j) * 66 + lane * 2]);
                mma_tf32(accO[j], a0, a1, a2, a3,
                         __float_as_uint(bb.x), __float_as_uint(bb.y));
            }
        }
        __syncwarp();   // P block reusable next iter only after all lanes done
    }

    // epilogue: att = rna_tf32(O / l)
    const float inv0 = 1.f / lrow0;
    const float inv1 = 1.f / lrow1;
    float* obase = att + ((long)(b * LL + m0 + warp * 16 + g)) * DD + h * HD;
#pragma unroll
    for (int j = 0; j < 8; j++) {
        const int c = j * 8 + tg * 2;
        *reinterpret_cast<float2*>(&obase[c]) =
            make_float2(to_tf32(accO[j][0] * inv0), to_tf32(accO[j][1] * inv0));
        *reinterpret_cast<float2*>(&obase[(long)8 * DD + c]) =
            make_float2(to_tf32(accO[j][2] * inv1), to_tf32(accO[j][3] * inv1));
    }
}

// ---------------------------------------------------------------------------
// RMSNorm
// ---------------------------------------------------------------------------
__global__ void rmsnorm_kernel(const float* __restrict__ x,
                               const float* __restrict__ scale,
                               float* __restrict__ out)
{
    const int row = blockIdx.x;
    const float4 a = *((const float4*)(x + (long)row * DD) + threadIdx.x);
    float ss = a.x * a.x + a.y * a.y + a.z * a.z + a.w * a.w;

    __shared__ float red[8];
    for (int o = 16; o > 0; o >>= 1) ss += __shfl_xor_sync(~0u, ss, o);
    if ((threadIdx.x & 31) == 0) red[threadIdx.x >> 5] = ss;
    __syncthreads();
    __shared__ float rinv;
    if (threadIdx.x == 0) {
        float t = 0.f;
#pragma unroll
        for (int i = 0; i < 8; i++) t += red[i];
        rinv = rsqrtf(t * (1.0f / DD) + EPS);
    }
    __syncthreads();

    const float4 sc = *((const float4*)scale + threadIdx.x);
    float4 o4;
    o4.x = a.x * rinv * sc.x; o4.y = a.y * rinv * sc.y;
    o4.z = a.z * rinv * sc.z; o4.w = a.w * rinv * sc.w;
    *((float4*)(out + (long)row * DD) + threadIdx.x) = o4;
}

// ---------------------------------------------------------------------------
// AdaLN modulation — emits tf32-rounded xm
// ---------------------------------------------------------------------------
__global__ void modulate_kernel(const float* __restrict__ xn,
                                const float* __restrict__ cp,
                                float* __restrict__ xm)
{
    const int idx = blockIdx.x * blockDim.x + threadIdx.x;
    const int row = idx >> 10;
    const int d = idx & 1023;
    const long base = (long)row * (3 * DD) + 3 * d;
    xm[idx] = to_tf32(xn[idx] * (1.f + cp[base]) + cp[base + 1]);
}

// ---------------------------------------------------------------------------
// RoPE + head scatter — emits tf32-rounded q (x0.125), kT, v
// ---------------------------------------------------------------------------
__global__ void rope_kernel(const float* __restrict__ qkv,
                            const float* __restrict__ pos,
                            float* __restrict__ q,
                            float* __restrict__ kT,
                            float* __restrict__ v)
{
    const int bl = blockIdx.x;
    const int b = bl >> 11;
    const int l = bl & (LL - 1);
    __shared__ float srow[3 * DD];
    __shared__ float spos[2 * HD];

    const float4* src = (const float4*)(qkv + (long)bl * (3 * DD));
    for (int i = threadIdx.x; i < (3 * DD) / 4; i += blockDim.x)
        ((float4*)srow)[i] = src[i];
    if (threadIdx.x < (2 * HD) / 4)
        ((float4*)spos)[threadIdx.x] =
            ((const float4*)(pos + (long)bl * (2 * HD)))[threadIdx.x];
    __syncthreads();

    for (int idx = threadIdx.x; idx < DD; idx += blockDim.x) {
        const int h = idx >> 6;
        const int d = idx & (HD - 1);
        const int c = (d * HH + h) * 3;
        const int dp = (d < HD / 2) ? d + HD / 2 : d - HD / 2;
        const int c2 = (dp * HH + h) * 3;
        const float sgn = (d < HD / 2) ? -1.f : 1.f;
        const float s = spos[2 * d];
        const float ct = spos[2 * d + 1];

        const float qo = srow[c] * ct + sgn * srow[c2] * s;
        const float ko = srow[c + 1] * ct + sgn * srow[c2 + 1] * s;

        const long o = ((long)(b * HH + h) * LL + l) * HD + d;
        q[o] = to_tf32(qo * 0.125f);
        kT[((long)(b * HH + h) * HD + d) * LL + l] = to_tf32(ko);
        v[o] = to_tf32(srow[c + 2]);
    }
}

// ---------------------------------------------------------------------------
// Launch
// ---------------------------------------------------------------------------
extern "C" void kernel_launch(void* const* d_in, const int* in_sizes, int n_in,
                              void* d_out, int out_size)
{
    const float* x         = (const float*)d_in[0];
    const float* cond      = (const float*)d_in[1];
    const float* pos       = (const float*)d_in[2];
    const float* rms_scale = (const float*)d_in[3];
    const float* W_cond    = (const float*)d_in[4];
    const float* W_qkv     = (const float*)d_in[5];
    const float* W_out     = (const float*)d_in[6];
    float* out = (float*)d_out;

    float *xn, *cp, *xm, *qkv, *q, *kT, *v, *att, *cr, *wc, *wq, *wo;
    cudaGetSymbolAddress((void**)&xn,  g_xn);
    cudaGetSymbolAddress((void**)&cp,  g_cp);
    cudaGetSymbolAddress((void**)&xm,  g_xm);
    cudaGetSymbolAddress((void**)&qkv, g_qkv);
    cudaGetSymbolAddress((void**)&q,   g_q);
    cudaGetSymbolAddress((void**)&kT,  g_kT);
    cudaGetSymbolAddress((void**)&v,   g_v);
    cudaGetSymbolAddress((void**)&att, g_att);
    cudaGetSymbolAddress((void**)&cr,  g_cr);
    cudaGetSymbolAddress((void**)&wc,  g_wc);
    cudaGetSymbolAddress((void**)&wq,  g_wq);
    cudaGetSymbolAddress((void**)&wo,  g_wo);

    static bool attr_set = false;
    if (!attr_set) {
        cudaFuncSetAttribute(flash_kernel,
                             cudaFuncAttributeMaxDynamicSharedMemorySize,
                             F_TOT * sizeof(float));
        cudaFuncSetAttribute(mma_gemm<128, 128, false>,
                             cudaFuncAttributeMaxDynamicSharedMemorySize,
                             MMA_SMEM_BYTES);
        cudaFuncSetAttribute(mma_gemm<128, 128, true>,
                             cudaFuncAttributeMaxDynamicSharedMemorySize,
                             MMA_SMEM_BYTES);
        attr_set = true;
    }

    // 0. tf32 pre-round of GEMM operands (weights + cond)
    round_kernel<<<(BL * DD) / 1024, 256>>>(cond, cr);
    round_kernel<<<(DD * 3 * DD) / 1024, 256>>>(W_cond, wc);
    round_kernel<<<(DD * 3 * DD) / 1024, 256>>>(W_qkv, wq);
    round_kernel<<<(DD * DD) / 1024, 256>>>(W_out, wo);

    // 1. RMSNorm
    rmsnorm_kernel<<<BL, 256>>>(x, rms_scale, xn);

    // 2. cond projection
    mma_gemm<128, 128, false><<<dim3(24, 32, 1), 256, MMA_SMEM_BYTES>>>(
        cr, wc, cp, DD, DD, 3 * DD, 3 * DD,
        0, 0, 1, 0, 0, nullptr, nullptr);

    // 3. modulate
    modulate_kernel<<<(BL * DD) / 256, 256>>>(xn, cp, xm);

    // 4. qkv projection
    mma_gemm<128, 128, false><<<dim3(24, 32, 1), 256, MMA_SMEM_BYTES>>>(
        xm, wq, qkv, DD, DD, 3 * DD, 3 * DD,
        0, 0, 1, 0, 0, nullptr, nullptr);

    // 5. RoPE + head scatter (tf32-rounded outputs)
    rope_kernel<<<BL, 256>>>(qkv, pos, q, kT, v);

    // 6-8. flash attention -> att [B,L,D] (tf32-rounded)
    flash_kernel<<<dim3(LL / 128, BB * HH), 256, F_TOT * sizeof(float)>>>(
        q, kT, v, att);

    // 9. out projection + residual + gate
    mma_gemm<128, 128, true><<<dim3(8, 32, 1), 256, MMA_SMEM_BYTES>>>(
        att, wo, out, DD, DD, DD, DD,
        0, 0, 1, 0, 0, x, cp);
}

// round 13
// speedup vs baseline: 1.1379x; 1.1379x over previous
#include <cuda_runtime.h>
#include <cuda_bf16.h>
#include <cstdint>

// ---------------------------------------------------------------------------
// Problem constants
// ---------------------------------------------------------------------------
#define BB 2
#define LL 2048
#define DD 1024
#define HH 16
#define HD 64
#define BL (BB*LL)           // 4096
#define EPS 1e-6f

// ---------------------------------------------------------------------------
// Scratch
// ---------------------------------------------------------------------------
__device__ float g_xn [BL*DD];
__device__ float g_cp [BL*3*DD];
__device__ float g_xm [BL*DD];             // modulated x, tf32-rounded
__device__ float g_qkv[BL*3*DD];
__device__ float g_q  [BL*DD];             // [B,H,L,HD], x0.125, tf32-rounded
__device__ float g_kT [BL*DD];             // [B,H,HD,L], tf32-rounded
__device__ float g_v  [BL*DD];             // [B,H,L,HD], tf32-rounded
__device__ float g_att[BL*DD];             // attn out [B,L,D], tf32-rounded
__device__ float g_cr [BL*DD];             // cond, tf32-rounded
__device__ float g_wc [DD*3*DD];           // W_cond, tf32-rounded
__device__ float g_wq [DD*3*DD];           // W_qkv, tf32-rounded
__device__ float g_wo [DD*DD];             // W_out, tf32-rounded

// ---------------------------------------------------------------------------
// helpers
// ---------------------------------------------------------------------------
__device__ __forceinline__ float to_tf32(float x) {
    uint32_t r;
    asm("cvt.rna.tf32.f32 %0, %1;" : "=r"(r) : "f"(x));
    return __uint_as_float(r);
}

__device__ __forceinline__ void mma_tf32(float acc[4],
                                         uint32_t a0, uint32_t a1, uint32_t a2, uint32_t a3,
                                         uint32_t b0, uint32_t b1) {
    asm volatile(
        "mma.sync.aligned.m16n8k8.row.col.f32.tf32.tf32.f32 "
        "{%0,%1,%2,%3}, {%4,%5,%6,%7}, {%8,%9}, {%0,%1,%2,%3};\n"
        : "+f"(acc[0]), "+f"(acc[1]), "+f"(acc[2]), "+f"(acc[3])
        : "r"(a0), "r"(a1), "r"(a2), "r"(a3), "r"(b0), "r"(b1));
}

__device__ __forceinline__ uint32_t smem_u32(const void* p) {
    return (uint32_t)__cvta_generic_to_shared(p);
}

#define CP_ASYNC16(dst_u32, src_ptr) \
    asm volatile("cp.async.cg.shared.global [%0], [%1], 16;\n" \
                 :: "r"(dst_u32), "l"(src_ptr))
#define CP_COMMIT() asm volatile("cp.async.commit_group;\n")
#define CP_WAIT1()  asm volatile("cp.async.wait_group 1;\n")
#define CP_WAIT0()  asm volatile("cp.async.wait_group 0;\n")

// GEMM smem sizing (BM=128, BN=128, BK=16, 3 stages) — dynamic smem
#define G_BK    16
#define G_NST   3
#define G_ASTR  (G_BK + 4)          // 20
#define G_BSTR  (128 + 8)           // 136
#define G_ASZ   (128 * G_ASTR)      // 2560 floats
#define G_BSZ   (G_BK * G_BSTR)     // 2176 floats
#define MMA_SMEM_BYTES ((G_NST * (G_ASZ + G_BSZ)) * (int)sizeof(float))  // 56832

// ---------------------------------------------------------------------------
// Fused tf32 pre-round of all GEMM operands (one launch, 4 segments)
// ---------------------------------------------------------------------------
#define R_C0 ((long)BL*DD/4)
#define R_C1 (R_C0 + (long)DD*3*DD/4)
#define R_C2 (R_C1 + (long)DD*3*DD/4)
#define R_C3 (R_C2 + (long)DD*DD/4)

__global__ void round_all(const float* __restrict__ cond, const float* __restrict__ Wc,
                          const float* __restrict__ Wq, const float* __restrict__ Wo,
                          float* __restrict__ cr, float* __restrict__ wc,
                          float* __restrict__ wq, float* __restrict__ wo)
{
    const long idx = (long)blockIdx.x * blockDim.x + threadIdx.x;
    const float4* src;
    float4* dst;
    long i;
    if (idx < R_C0)      { src = (const float4*)cond; dst = (float4*)cr; i = idx; }
    else if (idx < R_C1) { src = (const float4*)Wc;   dst = (float4*)wc; i = idx - R_C0; }
    else if (idx < R_C2) { src = (const float4*)Wq;   dst = (float4*)wq; i = idx - R_C1; }
    else                 { src = (const float4*)Wo;   dst = (float4*)wo; i = idx - R_C2; }
    float4 v = src[i];
    v.x = to_tf32(v.x); v.y = to_tf32(v.y);
    v.z = to_tf32(v.z); v.w = to_tf32(v.w);
    dst[i] = v;
}

// ---------------------------------------------------------------------------
// Batched tf32 tensor-core GEMM (NN), 3-stage cp.async pipeline (R10, verified)
// ---------------------------------------------------------------------------
template<int BM, int BN, bool EPI>
__global__ void __launch_bounds__(256)
mma_gemm(const float* __restrict__ A, const float* __restrict__ Bg,
         float* __restrict__ C,
         int K, int lda, int ldb, int ldc,
         long sA, long sB, int zmod, long sC_hi, long sC_lo,
         const float* __restrict__ Rres, const float* __restrict__ Gg)
{
    constexpr int BK = G_BK;
    constexpr int NST = G_NST;
    constexpr int WM = BM / 2;
    constexpr int WN = BN / 4;
    constexpr int MA = WM / 16;
    constexpr int NA = WN / 8;
    constexpr int ASTR = G_ASTR;
    constexpr int BSTR = BN + 8;
    constexpr int ASZ = BM * ASTR;
    constexpr int BSZ = BK * BSTR;

    extern __shared__ float gsm[];
    float* As = gsm;
    float* Bs = gsm + NST * ASZ;

    const int z = blockIdx.z;
    A += (long)z * sA;
    Bg += (long)z * sB;
    C += (long)(z / zmod) * sC_hi + (long)(z % zmod) * sC_lo;

    const int bm = blockIdx.y * BM;
    const int bn = blockIdx.x * BN;
    const int tid = threadIdx.x;
    const int lane = tid & 31;
    const int warp = tid >> 5;
    const int wm = warp >> 2;
    const int wn = warp & 3;
    const int g  = lane >> 2;
    const int tg = lane & 3;

    constexpr int A_IT = BM * BK / 1024;          // 2
    constexpr int A_RSTEP = 1024 / BK;            // 64
    const int arow = tid / (BK / 4);
    const int acol = (tid % (BK / 4)) * 4;
    constexpr int B_IT = BK * BN / 1024;          // 2
    constexpr int B_RSTEP = 1024 / BN;            // 8
    const int brow = tid / (BN / 4);
    const int bcol = (tid % (BN / 4)) * 4;

    float acc[MA][NA][4];
#pragma unroll
    for (int i = 0; i < MA; i++)
#pragma unroll
        for (int j = 0; j < NA; j++)
#pragma unroll
            for (int c = 0; c < 4; c++) acc[i][j][c] = 0.f;

    const int nk = K / BK;

#pragma unroll
    for (int s = 0; s < NST - 1; s++) {
        if (s < nk) {
            float* dA = As + s * ASZ;
            float* dB = Bs + s * BSZ;
#pragma unroll
            for (int i = 0; i < A_IT; i++)
                CP_ASYNC16(smem_u32(&dA[(arow + i * A_RSTEP) * ASTR + acol]),
                           &A[(long)(bm + arow + i * A_RSTEP) * lda + s * BK + acol]);
#pragma unroll
            for (int i = 0; i < B_IT; i++)
                CP_ASYNC16(smem_u32(&dB[(brow + i * B_RSTEP) * BSTR + bcol]),
                           &Bg[(long)(s * BK + brow + i * B_RSTEP) * ldb + bn + bcol]);
        }
        CP_COMMIT();
    }

    for (int it = 0; it < nk; it++) {
        CP_WAIT1();
        __syncthreads();

        const int t = it + NST - 1;
        if (t < nk) {
            const int fb = t % NST;
            float* dA = As + fb * ASZ;
            float* dB = Bs + fb * BSZ;
#pragma unroll
            for (int i = 0; i < A_IT; i++)
                CP_ASYNC16(smem_u32(&dA[(arow + i * A_RSTEP) * ASTR + acol]),
                           &A[(long)(bm + arow + i * A_RSTEP) * lda + t * BK + acol]);
#pragma unroll
            for (int i = 0; i < B_IT; i++)
                CP_ASYNC16(smem_u32(&dB[(brow + i * B_RSTEP) * BSTR + bcol]),
                           &Bg[(long)(t * BK + brow + i * B_RSTEP) * ldb + bn + bcol]);
        }
        CP_COMMIT();

        const int buf = it % NST;
        const float* cA = As + buf * ASZ;
        const float* cB = Bs + buf * BSZ;

#pragma unroll
        for (int ks = 0; ks < 2; ks++) {
            uint32_t af[MA][4], bf[NA][2];
#pragma unroll
            for (int i = 0; i < MA; i++) {
                const int r0 = (wm * WM + i * 16 + g) * ASTR + ks * 8 + tg;
                const int r1 = r0 + 8 * ASTR;
                af[i][0] = __float_as_uint(cA[r0]);
                af[i][1] = __float_as_uint(cA[r1]);
                af[i][2] = __float_as_uint(cA[r0 + 4]);
                af[i][3] = __float_as_uint(cA[r1 + 4]);
            }
#pragma unroll
            for (int j = 0; j < NA; j++) {
                const int c0 = (ks * 8 + tg) * BSTR + wn * WN + j * 8 + g;
                bf[j][0] = __float_as_uint(cB[c0]);
                bf[j][1] = __float_as_uint(cB[c0 + 4 * BSTR]);
            }
#pragma unroll
            for (int i = 0; i < MA; i++)
#pragma unroll
                for (int j = 0; j < NA; j++)
                    mma_tf32(acc[i][j], af[i][0], af[i][1], af[i][2], af[i][3],
                             bf[j][0], bf[j][1]);
        }
    }

#pragma unroll
    for (int i = 0; i < MA; i++) {
        const int r0 = bm + wm * WM + i * 16 + g;
#pragma unroll
        for (int j = 0; j < NA; j++) {
            const int c = bn + wn * WN + j * 8 + tg * 2;
            float2 v0 = make_float2(acc[i][j][0], acc[i][j][1]);
            float2 v1 = make_float2(acc[i][j][2], acc[i][j][3]);
            if (EPI) {
                v0.x += Rres[(long)r0 * DD + c]     + Gg[(long)r0 * 3 * DD + 3 * c + 2];
                v0.y += Rres[(long)r0 * DD + c + 1] + Gg[(long)r0 * 3 * DD + 3 * (c + 1) + 2];
                v1.x += Rres[(long)(r0 + 8) * DD + c]     + Gg[(long)(r0 + 8) * 3 * DD + 3 * c + 2];
                v1.y += Rres[(long)(r0 + 8) * DD + c + 1] + Gg[(long)(r0 + 8) * 3 * DD + 3 * (c + 1) + 2];
            }
            *reinterpret_cast<float2*>(&C[(long)r0 * ldc + c]) = v0;
            *reinterpret_cast<float2*>(&C[(long)(r0 + 8) * ldc + c]) = v1;
        }
    }
}

// ---------------------------------------------------------------------------
// Flash attention v3 (fixed K/V fill: 4 cp.asyncs per thread per tensor):
//   - K/V double-buffered via cp.async; ONE __syncthreads per chunk.
//   - P never touches smem: S C-frag -> P A-frag via quad shuffles.
//   - q/kT/v pre-rounded to tf32 by rope -> raw cp.async copies are exact.
// ---------------------------------------------------------------------------
#define F3_QSTR 68
#define F3_KSTR 72
#define F3_SQSZ (128 * F3_QSTR)          // 8704 floats
#define F3_KVSZ (2 * 64 * F3_KSTR)       // 9216 floats (K 4608 + V 4608)
#define F3_TOT  (F3_SQSZ + 2 * F3_KVSZ)  // 27136 floats = 108544 B

__global__ void __launch_bounds__(256, 2)
flash_kernel(const float* __restrict__ q, const float* __restrict__ kT,
             const float* __restrict__ v, float* __restrict__ att)
{
    extern __shared__ float sm[];
    float* sQ = sm;

    const int bh = blockIdx.y;
    const int b  = bh >> 4;
    const int h  = bh & (HH - 1);
    const int m0 = blockIdx.x * 128;
    const int tid = threadIdx.x;
    const int lane = tid & 31;
    const int warp = tid >> 5;
    const int g  = lane >> 2;
    const int tg = lane & 3;

    // ---- fill sQ (pre-rounded -> plain vectorized copy) ----
    const float* qbase = q + ((long)bh * LL + m0) * HD;
    for (int i = tid; i < 128 * 16; i += 256) {
        const int r = i >> 4, c4 = (i & 15) * 4;
        *reinterpret_cast<float4*>(&sQ[r * F3_QSTR + c4]) =
            *reinterpret_cast<const float4*>(&qbase[(long)r * HD + c4]);
    }

    const float* kbase = kT + (long)bh * HD * LL;
    const float* vbase = v + (long)bh * LL * HD;

    // fill indices: 64 rows x 64 cols; 4 threads/row, 4 float4s/thread
    const int frow = tid >> 2;            // 0..63
    const int fc0  = (tid & 3) * 4;       // 0,4,8,12 (+16*c)

    // ---- prologue: prefetch chunk 0 into buffer 0 ----
    {
        float* dK = sm + F3_SQSZ;
        float* dV = dK + 64 * F3_KSTR;
#pragma unroll
        for (int c = 0; c < 4; c++) {
            const int col = fc0 + c * 16;
            CP_ASYNC16(smem_u32(&dK[frow * F3_KSTR + col]),
                       &kbase[(long)frow * LL + col]);
            CP_ASYNC16(smem_u32(&dV[frow * F3_KSTR + col]),
                       &vbase[(long)frow * HD + col]);
        }
        CP_COMMIT();
    }

    float accO[8][4];
#pragma unroll
    for (int j = 0; j < 8; j++)
#pragma unroll
        for (int c = 0; c < 4; c++) accO[j][c] = 0.f;
    float mrow0 = -1e30f, mrow1 = -1e30f, lrow0 = 0.f, lrow1 = 0.f;

    const int qrow = (warp * 16 + g) * F3_QSTR;
    const int srcA = (lane & ~3) | (tg >> 1);
    const int srcB = srcA + 2;
    const bool esel = (tg & 1);

    for (int it = 0; it < 32; it++) {
        CP_WAIT0();
        __syncthreads();

        // prefetch chunk it+1 into the buffer freed at compute(it-1)
        if (it + 1 < 32) {
            const int j0n = (it + 1) * 64;
            float* dK = sm + F3_SQSZ + ((it + 1) & 1) * F3_KVSZ;
            float* dV = dK + 64 * F3_KSTR;
#pragma unroll
            for (int c = 0; c < 4; c++) {
                const int col = fc0 + c * 16;
                CP_ASYNC16(smem_u32(&dK[frow * F3_KSTR + col]),
                           &kbase[(long)frow * LL + j0n + col]);
                CP_ASYNC16(smem_u32(&dV[frow * F3_KSTR + col]),
                           &vbase[(long)(j0n + frow) * HD + col]);
            }
        }
        CP_COMMIT();

        const float* sK = sm + F3_SQSZ + (it & 1) * F3_KVSZ;
        const float* sV = sK + 64 * F3_KSTR;

        // ---- S = Q @ K^T (16x64 per warp, k=64) ----
        float s[8][4];
#pragma unroll
        for (int j = 0; j < 8; j++)
#pragma unroll
            for (int c = 0; c < 4; c++) s[j][c] = 0.f;
#pragma unroll
        for (int ks = 0; ks < 8; ks++) {
            const int r0 = qrow + ks * 8 + tg;
            const uint32_t a0 = __float_as_uint(sQ[r0]);
            const uint32_t a1 = __float_as_uint(sQ[r0 + 8 * F3_QSTR]);
            const uint32_t a2 = __float_as_uint(sQ[r0 + 4]);
            const uint32_t a3 = __float_as_uint(sQ[r0 + 8 * F3_QSTR + 4]);
#pragma unroll
            for (int j = 0; j < 8; j++) {
                const int c0 = (ks * 8 + tg) * F3_KSTR + j * 8 + g;
                mma_tf32(s[j], a0, a1, a2, a3,
                         __float_as_uint(sK[c0]),
                         __float_as_uint(sK[c0 + 4 * F3_KSTR]));
            }
        }

        // ---- online softmax (rows g / g+8; quad reduction) ----
        float mx0 = -1e30f, mx1 = -1e30f;
#pragma unroll
        for (int j = 0; j < 8; j++) {
            mx0 = fmaxf(mx0, fmaxf(s[j][0], s[j][1]));
            mx1 = fmaxf(mx1, fmaxf(s[j][2], s[j][3]));
        }
        mx0 = fmaxf(mx0, __shfl_xor_sync(~0u, mx0, 1));
        mx0 = fmaxf(mx0, __shfl_xor_sync(~0u, mx0, 2));
        mx1 = fmaxf(mx1, __shfl_xor_sync(~0u, mx1, 1));
        mx1 = fmaxf(mx1, __shfl_xor_sync(~0u, mx1, 2));

        const float mn0 = fmaxf(mrow0, mx0);
        const float mn1 = fmaxf(mrow1, mx1);
        const float al0 = __expf(mrow0 - mn0);
        const float al1 = __expf(mrow1 - mn1);
        mrow0 = mn0; mrow1 = mn1;

        float ps0 = 0.f, ps1 = 0.f;
#pragma unroll
        for (int j = 0; j < 8; j++) {
            s[j][0] = __expf(s[j][0] - mn0);
            s[j][1] = __expf(s[j][1] - mn0);
            s[j][2] = __expf(s[j][2] - mn1);
            s[j][3] = __expf(s[j][3] - mn1);
            ps0 += s[j][0] + s[j][1];
            ps1 += s[j][2] + s[j][3];
        }
        ps0 += __shfl_xor_sync(~0u, ps0, 1);
        ps0 += __shfl_xor_sync(~0u, ps0, 2);
        ps1 += __shfl_xor_sync(~0u, ps1, 1);
        ps1 += __shfl_xor_sync(~0u, ps1, 2);
        lrow0 = lrow0 * al0 + ps0;
        lrow1 = lrow1 * al1 + ps1;

#pragma unroll
        for (int j = 0; j < 8; j++) {
            accO[j][0] *= al0; accO[j][1] *= al0;
            accO[j][2] *= al1; accO[j][3] *= al1;
        }

        // ---- round P to tf32 in registers (same rounding point as sP path) ----
#pragma unroll
        for (int j = 0; j < 8; j++) {
            s[j][0] = to_tf32(s[j][0]);
            s[j][1] = to_tf32(s[j][1]);
            s[j][2] = to_tf32(s[j][2]);
            s[j][3] = to_tf32(s[j][3]);
        }

        // ---- O += P @ V : P A-frags via quad shuffles, V from smem ----
#pragma unroll
        for (int ks = 0; ks < 8; ks++) {
            const float p0A = __shfl_sync(~0u, s[ks][0], srcA);
            const float p1A = __shfl_sync(~0u, s[ks][1], srcA);
            const float p2A = __shfl_sync(~0u, s[ks][2], srcA);
            const float p3A = __shfl_sync(~0u, s[ks][3], srcA);
            const float p0B = __shfl_sync(~0u, s[ks][0], srcB);
            const float p1B = __shfl_sync(~0u, s[ks][1], srcB);
            const float p2B = __shfl_sync(~0u, s[ks][2], srcB);
            const float p3B = __shfl_sync(~0u, s[ks][3], srcB);
            const uint32_t a0 = __float_as_uint(esel ? p1A : p0A);
            const uint32_t a1 = __float_as_uint(esel ? p3A : p2A);
            const uint32_t a2 = __float_as_uint(esel ? p1B : p0B);
            const uint32_t a3 = __float_as_uint(esel ? p3B : p2B);
#pragma unroll
            for (int j = 0; j < 8; j++) {
                const int c0 = (ks * 8 + tg) * F3_KSTR + j * 8 + g;
                mma_tf32(accO[j], a0, a1, a2, a3,
                         __float_as_uint(sV[c0]),
                         __float_as_uint(sV[c0 + 4 * F3_KSTR]));
            }
        }
    }

    // ---- epilogue: att = rna_tf32(O / l) ----
    const float inv0 = 1.f / lrow0;
    const float inv1 = 1.f / lrow1;
    float* obase = att + ((long)(b * LL + m0 + warp * 16 + g)) * DD + h * HD;
#pragma unroll
    for (int j = 0; j < 8; j++) {
        const int c = j * 8 + tg * 2;
        *reinterpret_cast<float2*>(&obase[c]) =
            make_float2(to_tf32(accO[j][0] * inv0), to_tf32(accO[j][1] * inv0));
        *reinterpret_cast<float2*>(&obase[(long)8 * DD + c]) =
            make_float2(to_tf32(accO[j][2] * inv1), to_tf32(accO[j][3] * inv1));
    }
}

// ---------------------------------------------------------------------------
// RMSNorm
// ---------------------------------------------------------------------------
__global__ void rmsnorm_kernel(const float* __restrict__ x,
                               const float* __restrict__ scale,
                               float* __restrict__ out)
{
    const int row = blockIdx.x;
    const float4 a = *((const float4*)(x + (long)row * DD) + threadIdx.x);
    float ss = a.x * a.x + a.y * a.y + a.z * a.z + a.w * a.w;

    __shared__ float red[8];
    for (int o = 16; o > 0; o >>= 1) ss += __shfl_xor_sync(~0u, ss, o);
    if ((threadIdx.x & 31) == 0) red[threadIdx.x >> 5] = ss;
    __syncthreads();
    __shared__ float rinv;
    if (threadIdx.x == 0) {
        float t = 0.f;
#pragma unroll
        for (int i = 0; i < 8; i++) t += red[i];
        rinv = rsqrtf(t * (1.0f / DD) + EPS);
    }
    __syncthreads();

    const float4 sc = *((const float4*)scale + threadIdx.x);
    float4 o4;
    o4.x = a.x * rinv * sc.x; o4.y = a.y * rinv * sc.y;
    o4.z = a.z * rinv * sc.z; o4.w = a.w * rinv * sc.w;
    *((float4*)(out + (long)row * DD) + threadIdx.x) = o4;
}

// ---------------------------------------------------------------------------
// AdaLN modulation — emits tf32-rounded xm
// ---------------------------------------------------------------------------
__global__ void modulate_kernel(const float* __restrict__ xn,
                                const float* __restrict__ cp,
                                float* __restrict__ xm)
{
    const int idx = blockIdx.x * blockDim.x + threadIdx.x;
    const int row = idx >> 10;
    const int d = idx & 1023;
    const long base = (long)row * (3 * DD) + 3 * d;
    xm[idx] = to_tf32(xn[idx] * (1.f + cp[base]) + cp[base + 1]);
}

// ---------------------------------------------------------------------------
// RoPE + head scatter — emits tf32-rounded q (x0.125), kT, v
// ---------------------------------------------------------------------------
__global__ void rope_kernel(const float* __restrict__ qkv,
                            const float* __restrict__ pos,
                            float* __restrict__ q,
                            float* __restrict__ kT,
                            float* __restrict__ v)
{
    const int bl = blockIdx.x;
    const int b = bl >> 11;
    const int l = bl & (LL - 1);
    __shared__ float srow[3 * DD];
    __shared__ float spos[2 * HD];

    const float4* src = (const float4*)(qkv + (long)bl * (3 * DD));
    for (int i = threadIdx.x; i < (3 * DD) / 4; i += blockDim.x)
        ((float4*)srow)[i] = src[i];
    if (threadIdx.x < (2 * HD) / 4)
        ((float4*)spos)[threadIdx.x] =
            ((const float4*)(pos + (long)bl * (2 * HD)))[threadIdx.x];
    __syncthreads();

    for (int idx = threadIdx.x; idx < DD; idx += blockDim.x) {
        const int h = idx >> 6;
        const int d = idx & (HD - 1);
        const int c = (d * HH + h) * 3;
        const int dp = (d < HD / 2) ? d + HD / 2 : d - HD / 2;
        const int c2 = (dp * HH + h) * 3;
        const float sgn = (d < HD / 2) ? -1.f : 1.f;
        const float s = spos[2 * d];
        const float ct = spos[2 * d + 1];

        const float qo = srow[c] * ct + sgn * srow[c2] * s;
        const float ko = srow[c + 1] * ct + sgn * srow[c2 + 1] * s;

        const long o = ((long)(b * HH + h) * LL + l) * HD + d;
        q[o] = to_tf32(qo * 0.125f);
        kT[((long)(b * HH + h) * HD + d) * LL + l] = to_tf32(ko);
        v[o] = to_tf32(srow[c + 2]);
    }
}

// ---------------------------------------------------------------------------
// Launch
// ---------------------------------------------------------------------------
extern "C" void kernel_launch(void* const* d_in, const int* in_sizes, int n_in,
                              void* d_out, int out_size)
{
    const float* x         = (const float*)d_in[0];
    const float* cond      = (const float*)d_in[1];
    const float* pos       = (const float*)d_in[2];
    const float* rms_scale = (const float*)d_in[3];
    const float* W_cond    = (const float*)d_in[4];
    const float* W_qkv     = (const float*)d_in[5];
    const float* W_out     = (const float*)d_in[6];
    float* out = (float*)d_out;

    float *xn, *cp, *xm, *qkv, *q, *kT, *v, *att, *cr, *wc, *wq, *wo;
    cudaGetSymbolAddress((void**)&xn,  g_xn);
    cudaGetSymbolAddress((void**)&cp,  g_cp);
    cudaGetSymbolAddress((void**)&xm,  g_xm);
    cudaGetSymbolAddress((void**)&qkv, g_qkv);
    cudaGetSymbolAddress((void**)&q,   g_q);
    cudaGetSymbolAddress((void**)&kT,  g_kT);
    cudaGetSymbolAddress((void**)&v,   g_v);
    cudaGetSymbolAddress((void**)&att, g_att);
    cudaGetSymbolAddress((void**)&cr,  g_cr);
    cudaGetSymbolAddress((void**)&wc,  g_wc);
    cudaGetSymbolAddress((void**)&wq,  g_wq);
    cudaGetSymbolAddress((void**)&wo,  g_wo);

    static bool attr_set = false;
    if (!attr_set) {
        cudaFuncSetAttribute(flash_kernel,
                             cudaFuncAttributeMaxDynamicSharedMemorySize,
                             F3_TOT * sizeof(float));
        cudaFuncSetAttribute(mma_gemm<128, 128, false>,
                             cudaFuncAttributeMaxDynamicSharedMemorySize,
                             MMA_SMEM_BYTES);
        cudaFuncSetAttribute(mma_gemm<128, 128, true>,
                             cudaFuncAttributeMaxDynamicSharedMemorySize,
                             MMA_SMEM_BYTES);
        attr_set = true;
    }

    // 0. fused tf32 pre-round (cond + all three weights, one launch)
    round_all<<<(int)(R_C3 / 256), 256>>>(cond, W_cond, W_qkv, W_out,
                                          cr, wc, wq, wo);

    // 1. RMSNorm
    rmsnorm_kernel<<<BL, 256>>>(x, rms_scale, xn);

    // 2. cond projection
    mma_gemm<128, 128, false><<<dim3(24, 32, 1), 256, MMA_SMEM_BYTES>>>(
        cr, wc, cp, DD, DD, 3 * DD, 3 * DD,
        0, 0, 1, 0, 0, nullptr, nullptr);

    // 3. modulate
    modulate_kernel<<<(BL * DD) / 256, 256>>>(xn, cp, xm);

    // 4. qkv projection
    mma_gemm<128, 128, false><<<dim3(24, 32, 1), 256, MMA_SMEM_BYTES>>>(
        xm, wq, qkv, DD, DD, 3 * DD, 3 * DD,
        0, 0, 1, 0, 0, nullptr, nullptr);

    // 5. RoPE + head scatter (tf32-rounded outputs)
    rope_kernel<<<BL, 256>>>(qkv, pos, q, kT, v);

    // 6-8. flash attention v3 -> att [B,L,D] (tf32-rounded)
    flash_kernel<<<dim3(LL / 128, BB * HH), 256, F3_TOT * sizeof(float)>>>(
        q, kT, v, att);

    // 9. out projection + residual + gate
    mma_gemm<128, 128, true><<<dim3(8, 32, 1), 256, MMA_SMEM_BYTES>>>(
        att, wo, out, DD, DD, DD, DD,
        0, 0, 1, 0, 0, x, cp);
}

// round 14
// speedup vs baseline: 1.1593x; 1.0188x over previous
#include <cuda_runtime.h>
#include <cuda_bf16.h>
#include <cstdint>

// ---------------------------------------------------------------------------
// Problem constants
// ---------------------------------------------------------------------------
#define BB 2
#define LL 2048
#define DD 1024
#define HH 16
#define HD 64
#define BL (BB*LL)           // 4096
#define EPS 1e-6f

// ---------------------------------------------------------------------------
// Scratch
// ---------------------------------------------------------------------------
__device__ float g_xn [BL*DD];
__device__ float g_cp [BL*3*DD];           // PLANAR: [scale | shift | gate] per row
__device__ float g_xm [BL*DD];             // modulated x, tf32-rounded
__device__ float g_qkv[BL*3*DD];
__device__ float g_q  [BL*DD];             // [B,H,L,HD], x0.125, tf32-rounded
__device__ float g_k  [BL*DD];             // [B,H,L,HD], tf32-rounded
__device__ float g_v  [BL*DD];             // [B,H,L,HD], tf32-rounded
__device__ float g_att[BL*DD];             // attn out [B,L,D], tf32-rounded
__device__ float g_cr [BL*DD];             // cond, tf32-rounded
__device__ float g_wc [DD*3*DD];           // W_cond, tf32-rounded, columns planar-permuted
__device__ float g_wq [DD*3*DD];           // W_qkv, tf32-rounded
__device__ float g_wo [DD*DD];             // W_out, tf32-rounded

// ---------------------------------------------------------------------------
// helpers
// ---------------------------------------------------------------------------
__device__ __forceinline__ float to_tf32(float x) {
    uint32_t r;
    asm("cvt.rna.tf32.f32 %0, %1;" : "=r"(r) : "f"(x));
    return __uint_as_float(r);
}

__device__ __forceinline__ void mma_tf32(float acc[4],
                                         uint32_t a0, uint32_t a1, uint32_t a2, uint32_t a3,
                                         uint32_t b0, uint32_t b1) {
    asm volatile(
        "mma.sync.aligned.m16n8k8.row.col.f32.tf32.tf32.f32 "
        "{%0,%1,%2,%3}, {%4,%5,%6,%7}, {%8,%9}, {%0,%1,%2,%3};\n"
        : "+f"(acc[0]), "+f"(acc[1]), "+f"(acc[2]), "+f"(acc[3])
        : "r"(a0), "r"(a1), "r"(a2), "r"(a3), "r"(b0), "r"(b1));
}

__device__ __forceinline__ uint32_t smem_u32(const void* p) {
    return (uint32_t)__cvta_generic_to_shared(p);
}

#define CP_ASYNC16(dst_u32, src_ptr) \
    asm volatile("cp.async.cg.shared.global [%0], [%1], 16;\n" \
                 :: "r"(dst_u32), "l"(src_ptr))
#define CP_COMMIT() asm volatile("cp.async.commit_group;\n")
#define CP_WAIT1()  asm volatile("cp.async.wait_group 1;\n")
#define CP_WAIT0()  asm volatile("cp.async.wait_group 0;\n")

// GEMM smem sizing (BM=128, BN=128, BK=16, 3 stages) — dynamic smem
#define G_BK    16
#define G_NST   3
#define G_ASTR  (G_BK + 4)          // 20
#define G_BSTR  (128 + 8)           // 136
#define G_ASZ   (128 * G_ASTR)      // 2560 floats
#define G_BSZ   (G_BK * G_BSTR)     // 2176 floats
#define MMA_SMEM_BYTES ((G_NST * (G_ASZ + G_BSZ)) * (int)sizeof(float))  // 56832

// ---------------------------------------------------------------------------
// Fused tf32 pre-round. W_cond columns permuted to planar: col 3d+s -> s*D+d
// so cp = cond @ wc comes out as [scale | shift | gate] planes per row.
// ---------------------------------------------------------------------------
#define R_C0 ((long)BL*DD/4)
#define R_C1 (R_C0 + (long)DD*3*DD/4)
#define R_C2 (R_C1 + (long)DD*3*DD/4)
#define R_C3 (R_C2 + (long)DD*DD/4)

__global__ void round_all(const float* __restrict__ cond, const float* __restrict__ Wc,
                          const float* __restrict__ Wq, const float* __restrict__ Wo,
                          float* __restrict__ cr, float* __restrict__ wc,
                          float* __restrict__ wq, float* __restrict__ wo)
{
    const long idx = (long)blockIdx.x * blockDim.x + threadIdx.x;
    if (idx < R_C0) {
        float4 v = ((const float4*)cond)[idx];
        v.x = to_tf32(v.x); v.y = to_tf32(v.y);
        v.z = to_tf32(v.z); v.w = to_tf32(v.w);
        ((float4*)cr)[idx] = v;
    } else if (idx < R_C1) {
        const long i = idx - R_C0;
        const int k  = (int)(i / (3 * DD / 4));
        const int j4 = (int)(i % (3 * DD / 4)) * 4;
        float4 v = ((const float4*)Wc)[i];
        float vals[4] = {v.x, v.y, v.z, v.w};
#pragma unroll
        for (int e = 0; e < 4; e++) {
            const int c = j4 + e;
            const int d = c / 3;
            const int s = c - d * 3;
            wc[(long)k * 3 * DD + s * DD + d] = to_tf32(vals[e]);
        }
    } else if (idx < R_C2) {
        const long i = idx - R_C1;
        float4 v = ((const float4*)Wq)[i];
        v.x = to_tf32(v.x); v.y = to_tf32(v.y);
        v.z = to_tf32(v.z); v.w = to_tf32(v.w);
        ((float4*)wq)[i] = v;
    } else {
        const long i = idx - R_C2;
        float4 v = ((const float4*)Wo)[i];
        v.x = to_tf32(v.x); v.y = to_tf32(v.y);
        v.z = to_tf32(v.z); v.w = to_tf32(v.w);
        ((float4*)wo)[i] = v;
    }
}

// ---------------------------------------------------------------------------
// Batched tf32 tensor-core GEMM (NN), 3-stage cp.async pipeline.
// EPI: C += residual + gate, gate read from PLANAR cp (coalesced float2).
// ---------------------------------------------------------------------------
template<int BM, int BN, bool EPI>
__global__ void __launch_bounds__(256)
mma_gemm(const float* __restrict__ A, const float* __restrict__ Bg,
         float* __restrict__ C,
         int K, int lda, int ldb, int ldc,
         long sA, long sB, int zmod, long sC_hi, long sC_lo,
         const float* __restrict__ Rres, const float* __restrict__ Gg)
{
    constexpr int BK = G_BK;
    constexpr int NST = G_NST;
    constexpr int WM = BM / 2;
    constexpr int WN = BN / 4;
    constexpr int MA = WM / 16;
    constexpr int NA = WN / 8;
    constexpr int ASTR = G_ASTR;
    constexpr int BSTR = BN + 8;
    constexpr int ASZ = BM * ASTR;
    constexpr int BSZ = BK * BSTR;

    extern __shared__ float gsm[];
    float* As = gsm;
    float* Bs = gsm + NST * ASZ;

    const int z = blockIdx.z;
    A += (long)z * sA;
    Bg += (long)z * sB;
    C += (long)(z / zmod) * sC_hi + (long)(z % zmod) * sC_lo;

    const int bm = blockIdx.y * BM;
    const int bn = blockIdx.x * BN;
    const int tid = threadIdx.x;
    const int lane = tid & 31;
    const int warp = tid >> 5;
    const int wm = warp >> 2;
    const int wn = warp & 3;
    const int g  = lane >> 2;
    const int tg = lane & 3;

    constexpr int A_IT = BM * BK / 1024;          // 2
    constexpr int A_RSTEP = 1024 / BK;            // 64
    const int arow = tid / (BK / 4);
    const int acol = (tid % (BK / 4)) * 4;
    constexpr int B_IT = BK * BN / 1024;          // 2
    constexpr int B_RSTEP = 1024 / BN;            // 8
    const int brow = tid / (BN / 4);
    const int bcol = (tid % (BN / 4)) * 4;

    float acc[MA][NA][4];
#pragma unroll
    for (int i = 0; i < MA; i++)
#pragma unroll
        for (int j = 0; j < NA; j++)
#pragma unroll
            for (int c = 0; c < 4; c++) acc[i][j][c] = 0.f;

    const int nk = K / BK;

#pragma unroll
    for (int s = 0; s < NST - 1; s++) {
        if (s < nk) {
            float* dA = As + s * ASZ;
            float* dB = Bs + s * BSZ;
#pragma unroll
            for (int i = 0; i < A_IT; i++)
                CP_ASYNC16(smem_u32(&dA[(arow + i * A_RSTEP) * ASTR + acol]),
                           &A[(long)(bm + arow + i * A_RSTEP) * lda + s * BK + acol]);
#pragma unroll
            for (int i = 0; i < B_IT; i++)
                CP_ASYNC16(smem_u32(&dB[(brow + i * B_RSTEP) * BSTR + bcol]),
                           &Bg[(long)(s * BK + brow + i * B_RSTEP) * ldb + bn + bcol]);
        }
        CP_COMMIT();
    }

    for (int it = 0; it < nk; it++) {
        CP_WAIT1();
        __syncthreads();

        const int t = it + NST - 1;
        if (t < nk) {
            const int fb = t % NST;
            float* dA = As + fb * ASZ;
            float* dB = Bs + fb * BSZ;
#pragma unroll
            for (int i = 0; i < A_IT; i++)
                CP_ASYNC16(smem_u32(&dA[(arow + i * A_RSTEP) * ASTR + acol]),
                           &A[(long)(bm + arow + i * A_RSTEP) * lda + t * BK + acol]);
#pragma unroll
            for (int i = 0; i < B_IT; i++)
                CP_ASYNC16(smem_u32(&dB[(brow + i * B_RSTEP) * BSTR + bcol]),
                           &Bg[(long)(t * BK + brow + i * B_RSTEP) * ldb + bn + bcol]);
        }
        CP_COMMIT();

        const int buf = it % NST;
        const float* cA = As + buf * ASZ;
        const float* cB = Bs + buf * BSZ;

#pragma unroll
        for (int ks = 0; ks < 2; ks++) {
            uint32_t af[MA][4], bf[NA][2];
#pragma unroll
            for (int i = 0; i < MA; i++) {
                const int r0 = (wm * WM + i * 16 + g) * ASTR + ks * 8 + tg;
                const int r1 = r0 + 8 * ASTR;
                af[i][0] = __float_as_uint(cA[r0]);
                af[i][1] = __float_as_uint(cA[r1]);
                af[i][2] = __float_as_uint(cA[r0 + 4]);
                af[i][3] = __float_as_uint(cA[r1 + 4]);
            }
#pragma unroll
            for (int j = 0; j < NA; j++) {
                const int c0 = (ks * 8 + tg) * BSTR + wn * WN + j * 8 + g;
                bf[j][0] = __float_as_uint(cB[c0]);
                bf[j][1] = __float_as_uint(cB[c0 + 4 * BSTR]);
            }
#pragma unroll
            for (int i = 0; i < MA; i++)
#pragma unroll
                for (int j = 0; j < NA; j++)
                    mma_tf32(acc[i][j], af[i][0], af[i][1], af[i][2], af[i][3],
                             bf[j][0], bf[j][1]);
        }
    }

#pragma unroll
    for (int i = 0; i < MA; i++) {
        const int r0 = bm + wm * WM + i * 16 + g;
#pragma unroll
        for (int j = 0; j < NA; j++) {
            const int c = bn + wn * WN + j * 8 + tg * 2;
            float2 v0 = make_float2(acc[i][j][0], acc[i][j][1]);
            float2 v1 = make_float2(acc[i][j][2], acc[i][j][3]);
            if (EPI) {
                const float2 rr0 = *reinterpret_cast<const float2*>(&Rres[(long)r0 * DD + c]);
                const float2 rr1 = *reinterpret_cast<const float2*>(&Rres[(long)(r0 + 8) * DD + c]);
                const float2 gg0 = *reinterpret_cast<const float2*>(&Gg[(long)r0 * 3 * DD + 2 * DD + c]);
                const float2 gg1 = *reinterpret_cast<const float2*>(&Gg[(long)(r0 + 8) * 3 * DD + 2 * DD + c]);
                v0.x += rr0.x + gg0.x;  v0.y += rr0.y + gg0.y;
                v1.x += rr1.x + gg1.x;  v1.y += rr1.y + gg1.y;
            }
            *reinterpret_cast<float2*>(&C[(long)r0 * ldc + c]) = v0;
            *reinterpret_cast<float2*>(&C[(long)(r0 + 8) * ldc + c]) = v1;
        }
    }
}

// ---------------------------------------------------------------------------
// Flash attention v4:
//   - persistent: 256 CTAs x 2 tiles (exactly one wave, no quantization tail)
//   - K stored [B,H,L,HD] (rope writes coalesced); sK is l-major with
//     stride 76 -> frag banks (12g+tg) form a perfect 32-bank partition
//   - K/V double-buffered cp.async, 1 barrier/chunk, P via quad shuffles
// ---------------------------------------------------------------------------
#define F3_QSTR 68
#define F3_KSTR 76
#define F3_VSTR 72
#define F3_SQSZ (128 * F3_QSTR)          // 8704
#define F3_KSZ  (64 * F3_KSTR)           // 4864
#define F3_VSZ  (64 * F3_VSTR)           // 4608
#define F3_KVSZ (F3_KSZ + F3_VSZ)        // 9472
#define F3_TOT  (F3_SQSZ + 2 * F3_KVSZ)  // 27648 floats = 110592 B

__global__ void __launch_bounds__(256, 2)
flash_kernel(const float* __restrict__ q, const float* __restrict__ k,
             const float* __restrict__ v, float* __restrict__ att)
{
    extern __shared__ float sm[];
    float* sQ = sm;

    const int tid = threadIdx.x;
    const int lane = tid & 31;
    const int warp = tid >> 5;
    const int g  = lane >> 2;
    const int tg = lane & 3;

    const int frow = tid >> 2;            // 0..63
    const int fc0  = (tid & 3) * 4;       // 0,4,8,12 (+16*c)

    const int qrow = (warp * 16 + g) * F3_QSTR;
    const int srcA = (lane & ~3) | (tg >> 1);
    const int srcB = srcA + 2;
    const bool esel = (tg & 1);

    for (int rep = 0; rep < 2; rep++) {
        const int tt = blockIdx.x + rep * 256;   // 0..511
        const int bh = tt >> 4;
        const int b  = bh >> 4;
        const int h  = bh & (HH - 1);
        const int m0 = (tt & 15) * 128;

        const float* qbase = q + ((long)bh * LL + m0) * HD;
        const float* kbase = k + (long)bh * LL * HD;
        const float* vbase = v + (long)bh * LL * HD;

        __syncthreads();   // previous tile fully done with sQ and KV buffers

        // ---- fill sQ (pre-rounded -> plain vectorized copy) ----
        for (int i = tid; i < 128 * 16; i += 256) {
            const int r = i >> 4, c4 = (i & 15) * 4;
            *reinterpret_cast<float4*>(&sQ[r * F3_QSTR + c4]) =
                *reinterpret_cast<const float4*>(&qbase[(long)r * HD + c4]);
        }

        // ---- prologue: prefetch chunk 0 into buffer 0 ----
        {
            float* dK = sm + F3_SQSZ;
            float* dV = dK + F3_KSZ;
#pragma unroll
            for (int c = 0; c < 4; c++) {
                const int col = fc0 + c * 16;
                CP_ASYNC16(smem_u32(&dK[frow * F3_KSTR + col]),
                           &kbase[(long)frow * HD + col]);
                CP_ASYNC16(smem_u32(&dV[frow * F3_VSTR + col]),
                           &vbase[(long)frow * HD + col]);
            }
            CP_COMMIT();
        }

        float accO[8][4];
#pragma unroll
        for (int j = 0; j < 8; j++)
#pragma unroll
            for (int c = 0; c < 4; c++) accO[j][c] = 0.f;
        float mrow0 = -1e30f, mrow1 = -1e30f, lrow0 = 0.f, lrow1 = 0.f;

        for (int it = 0; it < 32; it++) {
            CP_WAIT0();
            __syncthreads();

            if (it + 1 < 32) {
                const int j0n = (it + 1) * 64;
                float* dK = sm + F3_SQSZ + ((it + 1) & 1) * F3_KVSZ;
                float* dV = dK + F3_KSZ;
#pragma unroll
                for (int c = 0; c < 4; c++) {
                    const int col = fc0 + c * 16;
                    CP_ASYNC16(smem_u32(&dK[frow * F3_KSTR + col]),
                               &kbase[(long)(j0n + frow) * HD + col]);
                    CP_ASYNC16(smem_u32(&dV[frow * F3_VSTR + col]),
                               &vbase[(long)(j0n + frow) * HD + col]);
                }
            }
            CP_COMMIT();

            const float* sK = sm + F3_SQSZ + (it & 1) * F3_KVSZ;
            const float* sV = sK + F3_KSZ;

            // ---- S = Q @ K^T : B[k][n] = sK[n * 76 + k]  (K is l-major) ----
            float s[8][4];
#pragma unroll
            for (int j = 0; j < 8; j++)
#pragma unroll
                for (int c = 0; c < 4; c++) s[j][c] = 0.f;
#pragma unroll
            for (int ks = 0; ks < 8; ks++) {
                const int r0 = qrow + ks * 8 + tg;
                const uint32_t a0 = __float_as_uint(sQ[r0]);
                const uint32_t a1 = __float_as_uint(sQ[r0 + 8 * F3_QSTR]);
                const uint32_t a2 = __float_as_uint(sQ[r0 + 4]);
                const uint32_t a3 = __float_as_uint(sQ[r0 + 8 * F3_QSTR + 4]);
#pragma unroll
                for (int j = 0; j < 8; j++) {
                    const int c0 = (j * 8 + g) * F3_KSTR + ks * 8 + tg;
                    mma_tf32(s[j], a0, a1, a2, a3,
                             __float_as_uint(sK[c0]),
                             __float_as_uint(sK[c0 + 4]));
                }
            }

            // ---- online softmax (rows g / g+8; quad reduction) ----
            float mx0 = -1e30f, mx1 = -1e30f;
#pragma unroll
            for (int j = 0; j < 8; j++) {
                mx0 = fmaxf(mx0, fmaxf(s[j][0], s[j][1]));
                mx1 = fmaxf(mx1, fmaxf(s[j][2], s[j][3]));
            }
            mx0 = fmaxf(mx0, __shfl_xor_sync(~0u, mx0, 1));
            mx0 = fmaxf(mx0, __shfl_xor_sync(~0u, mx0, 2));
            mx1 = fmaxf(mx1, __shfl_xor_sync(~0u, mx1, 1));
            mx1 = fmaxf(mx1, __shfl_xor_sync(~0u, mx1, 2));

            const float mn0 = fmaxf(mrow0, mx0);
            const float mn1 = fmaxf(mrow1, mx1);
            const float al0 = __expf(mrow0 - mn0);
            const float al1 = __expf(mrow1 - mn1);
            mrow0 = mn0; mrow1 = mn1;

            float ps0 = 0.f, ps1 = 0.f;
#pragma unroll
            for (int j = 0; j < 8; j++) {
                s[j][0] = __expf(s[j][0] - mn0);
                s[j][1] = __expf(s[j][1] - mn0);
                s[j][2] = __expf(s[j][2] - mn1);
                s[j][3] = __expf(s[j][3] - mn1);
                ps0 += s[j][0] + s[j][1];
                ps1 += s[j][2] + s[j][3];
            }
            ps0 += __shfl_xor_sync(~0u, ps0, 1);
            ps0 += __shfl_xor_sync(~0u, ps0, 2);
            ps1 += __shfl_xor_sync(~0u, ps1, 1);
            ps1 += __shfl_xor_sync(~0u, ps1, 2);
            lrow0 = lrow0 * al0 + ps0;
            lrow1 = lrow1 * al1 + ps1;

#pragma unroll
            for (int j = 0; j < 8; j++) {
                accO[j][0] *= al0; accO[j][1] *= al0;
                accO[j][2] *= al1; accO[j][3] *= al1;
            }

            // ---- round P to tf32 in registers ----
#pragma unroll
            for (int j = 0; j < 8; j++) {
                s[j][0] = to_tf32(s[j][0]);
                s[j][1] = to_tf32(s[j][1]);
                s[j][2] = to_tf32(s[j][2]);
                s[j][3] = to_tf32(s[j][3]);
            }

            // ---- O += P @ V : P A-frags via quad shuffles ----
#pragma unroll
            for (int ks = 0; ks < 8; ks++) {
                const float p0A = __shfl_sync(~0u, s[ks][0], srcA);
                const float p1A = __shfl_sync(~0u, s[ks][1], srcA);
                const float p2A = __shfl_sync(~0u, s[ks][2], srcA);
                const float p3A = __shfl_sync(~0u, s[ks][3], srcA);
                const float p0B = __shfl_sync(~0u, s[ks][0], srcB);
                const float p1B = __shfl_sync(~0u, s[ks][1], srcB);
                const float p2B = __shfl_sync(~0u, s[ks][2], srcB);
                const float p3B = __shfl_sync(~0u, s[ks][3], srcB);
                const uint32_t a0 = __float_as_uint(esel ? p1A : p0A);
                const uint32_t a1 = __float_as_uint(esel ? p3A : p2A);
                const uint32_t a2 = __float_as_uint(esel ? p1B : p0B);
                const uint32_t a3 = __float_as_uint(esel ? p3B : p2B);
#pragma unroll
                for (int j = 0; j < 8; j++) {
                    const int c0 = (ks * 8 + tg) * F3_VSTR + j * 8 + g;
                    mma_tf32(accO[j], a0, a1, a2, a3,
                             __float_as_uint(sV[c0]),
                             __float_as_uint(sV[c0 + 4 * F3_VSTR]));
                }
            }
        }

        // ---- epilogue: att = rna_tf32(O / l) ----
        const float inv0 = 1.f / lrow0;
        const float inv1 = 1.f / lrow1;
        float* obase = att + ((long)(b * LL + m0 + warp * 16 + g)) * DD + h * HD;
#pragma unroll
        for (int j = 0; j < 8; j++) {
            const int c = j * 8 + tg * 2;
            *reinterpret_cast<float2*>(&obase[c]) =
                make_float2(to_tf32(accO[j][0] * inv0), to_tf32(accO[j][1] * inv0));
            *reinterpret_cast<float2*>(&obase[(long)8 * DD + c]) =
                make_float2(to_tf32(accO[j][2] * inv1), to_tf32(accO[j][3] * inv1));
        }
    }
}

// ---------------------------------------------------------------------------
// RMSNorm
// ---------------------------------------------------------------------------
__global__ void rmsnorm_kernel(const float* __restrict__ x,
                               const float* __restrict__ scale,
                               float* __restrict__ out)
{
    const int row = blockIdx.x;
    const float4 a = *((const float4*)(x + (long)row * DD) + threadIdx.x);
    float ss = a.x * a.x + a.y * a.y + a.z * a.z + a.w * a.w;

    __shared__ float red[8];
    for (int o = 16; o > 0; o >>= 1) ss += __shfl_xor_sync(~0u, ss, o);
    if ((threadIdx.x & 31) == 0) red[threadIdx.x >> 5] = ss;
    __syncthreads();
    __shared__ float rinv;
    if (threadIdx.x == 0) {
        float t = 0.f;
#pragma unroll
        for (int i = 0; i < 8; i++) t += red[i];
        rinv = rsqrtf(t * (1.0f / DD) + EPS);
    }
    __syncthreads();

    const float4 sc = *((const float4*)scale + threadIdx.x);
    float4 o4;
    o4.x = a.x * rinv * sc.x; o4.y = a.y * rinv * sc.y;
    o4.z = a.z * rinv * sc.z; o4.w = a.w * rinv * sc.w;
    *((float4*)(out + (long)row * DD) + threadIdx.x) = o4;
}

// ---------------------------------------------------------------------------
// AdaLN modulation — planar cp, fully vectorized; emits tf32-rounded xm
// ---------------------------------------------------------------------------
__global__ void modulate_kernel(const float* __restrict__ xn,
                                const float* __restrict__ cp,
                                float* __restrict__ xm)
{
    const int i = blockIdx.x * blockDim.x + threadIdx.x;      // float4 id
    const int row = i / (DD / 4);
    const int d4 = (i % (DD / 4)) * 4;
    const long base = (long)row * 3 * DD + d4;
    const float4 a  = *reinterpret_cast<const float4*>(&xn[(long)row * DD + d4]);
    const float4 sc = *reinterpret_cast<const float4*>(&cp[base]);
    const float4 sh = *reinterpret_cast<const float4*>(&cp[base + DD]);
    float4 o;
    o.x = to_tf32(a.x * (1.f + sc.x) + sh.x);
    o.y = to_tf32(a.y * (1.f + sc.y) + sh.y);
    o.z = to_tf32(a.z * (1.f + sc.z) + sh.z);
    o.w = to_tf32(a.w * (1.f + sc.w) + sh.w);
    *reinterpret_cast<float4*>(&xm[(long)row * DD + d4]) = o;
}

// ---------------------------------------------------------------------------
// RoPE + head scatter — all three outputs [B,H,L,HD], coalesced, tf32-rounded
// ---------------------------------------------------------------------------
__global__ void rope_kernel(const float* __restrict__ qkv,
                            const float* __restrict__ pos,
                            float* __restrict__ q,
                            float* __restrict__ k,
                            float* __restrict__ v)
{
    const int bl = blockIdx.x;
    const int b = bl >> 11;
    const int l = bl & (LL - 1);
    __shared__ float srow[3 * DD];
    __shared__ float spos[2 * HD];

    const float4* src = (const float4*)(qkv + (long)bl * (3 * DD));
    for (int i = threadIdx.x; i < (3 * DD) / 4; i += blockDim.x)
        ((float4*)srow)[i] = src[i];
    if (threadIdx.x < (2 * HD) / 4)
        ((float4*)spos)[threadIdx.x] =
            ((const float4*)(pos + (long)bl * (2 * HD)))[threadIdx.x];
    __syncthreads();

    for (int idx = threadIdx.x; idx < DD; idx += blockDim.x) {
        const int h = idx >> 6;
        const int d = idx & (HD - 1);
        const int c = (d * HH + h) * 3;
        const int dp = (d < HD / 2) ? d + HD / 2 : d - HD / 2;
        const int c2 = (dp * HH + h) * 3;
        const float sgn = (d < HD / 2) ? -1.f : 1.f;
        const float s = spos[2 * d];
        const float ct = spos[2 * d + 1];

        const float qo = srow[c] * ct + sgn * srow[c2] * s;
        const float ko = srow[c + 1] * ct + sgn * srow[c2 + 1] * s;

        const long o = ((long)(b * HH + h) * LL + l) * HD + d;
        q[o] = to_tf32(qo * 0.125f);
        k[o] = to_tf32(ko);
        v[o] = to_tf32(srow[c + 2]);
    }
}

// ---------------------------------------------------------------------------
// Launch
// ---------------------------------------------------------------------------
extern "C" void kernel_launch(void* const* d_in, const int* in_sizes, int n_in,
                              void* d_out, int out_size)
{
    const float* x         = (const float*)d_in[0];
    const float* cond      = (const float*)d_in[1];
    const float* pos       = (const float*)d_in[2];
    const float* rms_scale = (const float*)d_in[3];
    const float* W_cond    = (const float*)d_in[4];
    const float* W_qkv     = (const float*)d_in[5];
    const float* W_out     = (const float*)d_in[6];
    float* out = (float*)d_out;

    float *xn, *cp, *xm, *qkv, *q, *k, *v, *att, *cr, *wc, *wq, *wo;
    cudaGetSymbolAddress((void**)&xn,  g_xn);
    cudaGetSymbolAddress((void**)&cp,  g_cp);
    cudaGetSymbolAddress((void**)&xm,  g_xm);
    cudaGetSymbolAddress((void**)&qkv, g_qkv);
    cudaGetSymbolAddress((void**)&q,   g_q);
    cudaGetSymbolAddress((void**)&k,   g_k);
    cudaGetSymbolAddress((void**)&v,   g_v);
    cudaGetSymbolAddress((void**)&att, g_att);
    cudaGetSymbolAddress((void**)&cr,  g_cr);
    cudaGetSymbolAddress((void**)&wc,  g_wc);
    cudaGetSymbolAddress((void**)&wq,  g_wq);
    cudaGetSymbolAddress((void**)&wo,  g_wo);

    static bool attr_set = false;
    if (!attr_set) {
        cudaFuncSetAttribute(flash_kernel,
                             cudaFuncAttributeMaxDynamicSharedMemorySize,
                             F3_TOT * sizeof(float));
        cudaFuncSetAttribute(mma_gemm<128, 128, false>,
                             cudaFuncAttributeMaxDynamicSharedMemorySize,
                             MMA_SMEM_BYTES);
        cudaFuncSetAttribute(mma_gemm<128, 128, true>,
                             cudaFuncAttributeMaxDynamicSharedMemorySize,
                             MMA_SMEM_BYTES);
        attr_set = true;
    }

    // 0. fused tf32 pre-round (cond + weights; W_cond columns planar-permuted)
    round_all<<<(int)(R_C3 / 256), 256>>>(cond, W_cond, W_qkv, W_out,
                                          cr, wc, wq, wo);

    // 1. RMSNorm
    rmsnorm_kernel<<<BL, 256>>>(x, rms_scale, xn);

    // 2. cond projection (-> planar cp)
    mma_gemm<128, 128, false><<<dim3(24, 32, 1), 256, MMA_SMEM_BYTES>>>(
        cr, wc, cp, DD, DD, 3 * DD, 3 * DD,
        0, 0, 1, 0, 0, nullptr, nullptr);

    // 3. modulate (planar, vectorized)
    modulate_kernel<<<(BL * DD / 4) / 256, 256>>>(xn, cp, xm);

    // 4. qkv projection
    mma_gemm<128, 128, false><<<dim3(24, 32, 1), 256, MMA_SMEM_BYTES>>>(
        xm, wq, qkv, DD, DD, 3 * DD, 3 * DD,
        0, 0, 1, 0, 0, nullptr, nullptr);

    // 5. RoPE + head scatter (all coalesced, tf32-rounded)
    rope_kernel<<<BL, 256>>>(qkv, pos, q, k, v);

    // 6-8. flash attention v4 (persistent, one wave) -> att [B,L,D]
    flash_kernel<<<256, 256, F3_TOT * sizeof(float)>>>(q, k, v, att);

    // 9. out projection + residual + gate (planar gate)
    mma_gemm<128, 128, true><<<dim3(8, 32, 1), 256, MMA_SMEM_BYTES>>>(
        att, wo, out, DD, DD, DD, DD,
        0, 0, 1, 0, 0, x, cp);
}

// round 16
// speedup vs baseline: 1.2501x; 1.0784x over previous
#include <cuda_runtime.h>
#include <cuda_bf16.h>
#include <cstdint>

// ---------------------------------------------------------------------------
// Problem constants
// ---------------------------------------------------------------------------
#define BB 2
#define LL 2048
#define DD 1024
#define HH 16
#define HD 64
#define BL (BB*LL)           // 4096
#define EPS 1e-6f

// ---------------------------------------------------------------------------
// Scratch
// ---------------------------------------------------------------------------
__device__ float g_xn [BL*DD];
__device__ float g_cp [BL*3*DD];           // PLANAR: [scale | shift | gate] per row
__device__ float g_xm [BL*DD];             // modulated x, tf32-rounded
__device__ float g_qkv[BL*3*DD];
__device__ float g_q  [BL*DD];             // [B,H,L,HD], x0.125, tf32-rounded
__device__ float g_k  [BL*DD];             // [B,H,L,HD], tf32-rounded
__device__ float g_v  [BL*DD];             // [B,H,L,HD], tf32-rounded
__device__ float g_att[BL*DD];             // attn out [B,L,D], tf32-rounded
__device__ float g_cr [BL*DD];             // cond, tf32-rounded
__device__ float g_wc [DD*3*DD];           // W_cond, tf32-rounded, columns planar-permuted
__device__ float g_wq [DD*3*DD];           // W_qkv, tf32-rounded
__device__ float g_wo [DD*DD];             // W_out, tf32-rounded

// ---------------------------------------------------------------------------
// helpers
// ---------------------------------------------------------------------------
__device__ __forceinline__ float to_tf32(float x) {
    uint32_t r;
    asm("cvt.rna.tf32.f32 %0, %1;" : "=r"(r) : "f"(x));
    return __uint_as_float(r);
}

__device__ __forceinline__ void mma_tf32(float acc[4],
                                         uint32_t a0, uint32_t a1, uint32_t a2, uint32_t a3,
                                         uint32_t b0, uint32_t b1) {
    asm volatile(
        "mma.sync.aligned.m16n8k8.row.col.f32.tf32.tf32.f32 "
        "{%0,%1,%2,%3}, {%4,%5,%6,%7}, {%8,%9}, {%0,%1,%2,%3};\n"
        : "+f"(acc[0]), "+f"(acc[1]), "+f"(acc[2]), "+f"(acc[3])
        : "r"(a0), "r"(a1), "r"(a2), "r"(a3), "r"(b0), "r"(b1));
}

__device__ __forceinline__ uint32_t smem_u32(const void* p) {
    return (uint32_t)__cvta_generic_to_shared(p);
}

#define CP_ASYNC16(dst_u32, src_ptr) \
    asm volatile("cp.async.cg.shared.global [%0], [%1], 16;\n" \
                 :: "r"(dst_u32), "l"(src_ptr))
#define CP_COMMIT() asm volatile("cp.async.commit_group;\n")
#define CP_WAIT0()  asm volatile("cp.async.wait_group 0;\n")

// GEMM smem sizing (BM=128, BN=128, BK=32, 2 stages, double buffer)
#define G_BK    32
#define G_NST   2
#define G_ASTR  (G_BK + 4)          // 36
#define G_BSTR  (128 + 8)           // 136
#define G_ASZ   (128 * G_ASTR)      // 4608 floats
#define G_BSZ   (G_BK * G_BSTR)     // 4352 floats
#define MMA_SMEM_BYTES ((G_NST * (G_ASZ + G_BSZ)) * (int)sizeof(float))  // 71680

// ---------------------------------------------------------------------------
// Fused tf32 pre-round. W_cond columns permuted to planar: col 3d+s -> s*D+d
// ---------------------------------------------------------------------------
#define R_C0 ((long)BL*DD/4)
#define R_C1 (R_C0 + (long)DD*3*DD/4)
#define R_C2 (R_C1 + (long)DD*3*DD/4)
#define R_C3 (R_C2 + (long)DD*DD/4)

__global__ void round_all(const float* __restrict__ cond, const float* __restrict__ Wc,
                          const float* __restrict__ Wq, const float* __restrict__ Wo,
                          float* __restrict__ cr, float* __restrict__ wc,
                          float* __restrict__ wq, float* __restrict__ wo)
{
    const long idx = (long)blockIdx.x * blockDim.x + threadIdx.x;
    if (idx < R_C0) {
        float4 v = ((const float4*)cond)[idx];
        v.x = to_tf32(v.x); v.y = to_tf32(v.y);
        v.z = to_tf32(v.z); v.w = to_tf32(v.w);
        ((float4*)cr)[idx] = v;
    } else if (idx < R_C1) {
        const long i = idx - R_C0;
        const int k  = (int)(i / (3 * DD / 4));
        const int j4 = (int)(i % (3 * DD / 4)) * 4;
        float4 v = ((const float4*)Wc)[i];
        float vals[4] = {v.x, v.y, v.z, v.w};
#pragma unroll
        for (int e = 0; e < 4; e++) {
            const int c = j4 + e;
            const int d = c / 3;
            const int s = c - d * 3;
            wc[(long)k * 3 * DD + s * DD + d] = to_tf32(vals[e]);
        }
    } else if (idx < R_C2) {
        const long i = idx - R_C1;
        float4 v = ((const float4*)Wq)[i];
        v.x = to_tf32(v.x); v.y = to_tf32(v.y);
        v.z = to_tf32(v.z); v.w = to_tf32(v.w);
        ((float4*)wq)[i] = v;
    } else {
        const long i = idx - R_C2;
        float4 v = ((const float4*)Wo)[i];
        v.x = to_tf32(v.x); v.y = to_tf32(v.y);
        v.z = to_tf32(v.z); v.w = to_tf32(v.w);
        ((float4*)wo)[i] = v;
    }
}

// ---------------------------------------------------------------------------
// Batched tf32 tensor-core GEMM (NN), BK=32, 2-stage double-buffered cp.async,
// ONE __syncthreads per K-tile (same verified invariant as flash v4).
// EPI: C += residual + gate (planar cp, coalesced float2).
// ---------------------------------------------------------------------------
template<int BM, int BN, bool EPI>
__global__ void __launch_bounds__(256)
mma_gemm(const float* __restrict__ A, const float* __restrict__ Bg,
         float* __restrict__ C,
         int K, int lda, int ldb, int ldc,
         long sA, long sB, int zmod, long sC_hi, long sC_lo,
         const float* __restrict__ Rres, const float* __restrict__ Gg)
{
    constexpr int BK = G_BK;
    constexpr int WM = BM / 2;
    constexpr int WN = BN / 4;
    constexpr int MA = WM / 16;
    constexpr int NA = WN / 8;
    constexpr int ASTR = G_ASTR;
    constexpr int BSTR = BN + 8;
    constexpr int ASZ = BM * ASTR;
    constexpr int BSZ = BK * BSTR;

    extern __shared__ float gsm[];
    float* As = gsm;                     // 2 * ASZ
    float* Bs = gsm + 2 * ASZ;           // 2 * BSZ

    const int z = blockIdx.z;
    A += (long)z * sA;
    Bg += (long)z * sB;
    C += (long)(z / zmod) * sC_hi + (long)(z % zmod) * sC_lo;

    const int bm = blockIdx.y * BM;
    const int bn = blockIdx.x * BN;
    const int tid = threadIdx.x;
    const int lane = tid & 31;
    const int warp = tid >> 5;
    const int wm = warp >> 2;
    const int wn = warp & 3;
    const int g  = lane >> 2;
    const int tg = lane & 3;

    constexpr int A_IT = BM * BK / 1024;          // 4
    constexpr int A_RSTEP = 1024 / BK;            // 32
    const int arow = tid / (BK / 4);              // tid/8
    const int acol = (tid % (BK / 4)) * 4;
    constexpr int B_IT = BK * BN / 1024;          // 4
    constexpr int B_RSTEP = 1024 / BN;            // 8
    const int brow = tid / (BN / 4);              // tid/32
    const int bcol = (tid % (BN / 4)) * 4;

    float acc[MA][NA][4];
#pragma unroll
    for (int i = 0; i < MA; i++)
#pragma unroll
        for (int j = 0; j < NA; j++)
#pragma unroll
            for (int c = 0; c < 4; c++) acc[i][j][c] = 0.f;

    const int nk = K / BK;

    // prologue: fill stage 0 into buffer 0
    {
        float* dA = As;
        float* dB = Bs;
#pragma unroll
        for (int i = 0; i < A_IT; i++)
            CP_ASYNC16(smem_u32(&dA[(arow + i * A_RSTEP) * ASTR + acol]),
                       &A[(long)(bm + arow + i * A_RSTEP) * lda + acol]);
#pragma unroll
        for (int i = 0; i < B_IT; i++)
            CP_ASYNC16(smem_u32(&dB[(brow + i * B_RSTEP) * BSTR + bcol]),
                       &Bg[(long)(brow + i * B_RSTEP) * ldb + bn + bcol]);
        CP_COMMIT();
    }

    for (int it = 0; it < nk; it++) {
        CP_WAIT0();            // stage `it` resident (all committed groups done)
        __syncthreads();       // all warps done computing iter it-1

        // prefetch stage it+1 into the buffer vacated at compute(it-1)
        if (it + 1 < nk) {
            const int fb = (it + 1) & 1;
            float* dA = As + fb * ASZ;
            float* dB = Bs + fb * BSZ;
            const long k0 = (long)(it + 1) * BK;
#pragma unroll
            for (int i = 0; i < A_IT; i++)
                CP_ASYNC16(smem_u32(&dA[(arow + i * A_RSTEP) * ASTR + acol]),
                           &A[(long)(bm + arow + i * A_RSTEP) * lda + k0 + acol]);
#pragma unroll
            for (int i = 0; i < B_IT; i++)
                CP_ASYNC16(smem_u32(&dB[(brow + i * B_RSTEP) * BSTR + bcol]),
                           &Bg[(k0 + brow + i * B_RSTEP) * ldb + bn + bcol]);
        }
        CP_COMMIT();

        const int buf = it & 1;
        const float* cA = As + buf * ASZ;
        const float* cB = Bs + buf * BSZ;

#pragma unroll
        for (int ks = 0; ks < 4; ks++) {
            uint32_t af[MA][4], bf[NA][2];
#pragma unroll
            for (int i = 0; i < MA; i++) {
                const int r0 = (wm * WM + i * 16 + g) * ASTR + ks * 8 + tg;
                const int r1 = r0 + 8 * ASTR;
                af[i][0] = __float_as_uint(cA[r0]);
                af[i][1] = __float_as_uint(cA[r1]);
                af[i][2] = __float_as_uint(cA[r0 + 4]);
                af[i][3] = __float_as_uint(cA[r1 + 4]);
            }
#pragma unroll
            for (int j = 0; j < NA; j++) {
                const int c0 = (ks * 8 + tg) * BSTR + wn * WN + j * 8 + g;
                bf[j][0] = __float_as_uint(cB[c0]);
                bf[j][1] = __float_as_uint(cB[c0 + 4 * BSTR]);
            }
#pragma unroll
            for (int i = 0; i < MA; i++)
#pragma unroll
                for (int j = 0; j < NA; j++)
                    mma_tf32(acc[i][j], af[i][0], af[i][1], af[i][2], af[i][3],
                             bf[j][0], bf[j][1]);
        }
    }

#pragma unroll
    for (int i = 0; i < MA; i++) {
        const int r0 = bm + wm * WM + i * 16 + g;
#pragma unroll
        for (int j = 0; j < NA; j++) {
            const int c = bn + wn * WN + j * 8 + tg * 2;
            float2 v0 = make_float2(acc[i][j][0], acc[i][j][1]);
            float2 v1 = make_float2(acc[i][j][2], acc[i][j][3]);
            if (EPI) {
                const float2 rr0 = *reinterpret_cast<const float2*>(&Rres[(long)r0 * DD + c]);
                const float2 rr1 = *reinterpret_cast<const float2*>(&Rres[(long)(r0 + 8) * DD + c]);
                const float2 gg0 = *reinterpret_cast<const float2*>(&Gg[(long)r0 * 3 * DD + 2 * DD + c]);
                const float2 gg1 = *reinterpret_cast<const float2*>(&Gg[(long)(r0 + 8) * 3 * DD + 2 * DD + c]);
                v0.x += rr0.x + gg0.x;  v0.y += rr0.y + gg0.y;
                v1.x += rr1.x + gg1.x;  v1.y += rr1.y + gg1.y;
            }
            *reinterpret_cast<float2*>(&C[(long)r0 * ldc + c]) = v0;
            *reinterpret_cast<float2*>(&C[(long)(r0 + 8) * ldc + c]) = v1;
        }
    }
}

// ---------------------------------------------------------------------------
// Flash attention v4 (verified R14; unchanged)
// ---------------------------------------------------------------------------
#define F3_QSTR 68
#define F3_KSTR 76
#define F3_VSTR 72
#define F3_SQSZ (128 * F3_QSTR)
#define F3_KSZ  (64 * F3_KSTR)
#define F3_VSZ  (64 * F3_VSTR)
#define F3_KVSZ (F3_KSZ + F3_VSZ)
#define F3_TOT  (F3_SQSZ + 2 * F3_KVSZ)

__global__ void __launch_bounds__(256, 2)
flash_kernel(const float* __restrict__ q, const float* __restrict__ k,
             const float* __restrict__ v, float* __restrict__ att)
{
    extern __shared__ float sm[];
    float* sQ = sm;

    const int tid = threadIdx.x;
    const int lane = tid & 31;
    const int warp = tid >> 5;
    const int g  = lane >> 2;
    const int tg = lane & 3;

    const int frow = tid >> 2;
    const int fc0  = (tid & 3) * 4;

    const int qrow = (warp * 16 + g) * F3_QSTR;
    const int srcA = (lane & ~3) | (tg >> 1);
    const int srcB = srcA + 2;
    const bool esel = (tg & 1);

    for (int rep = 0; rep < 2; rep++) {
        const int tt = blockIdx.x + rep * 256;
        const int bh = tt >> 4;
        const int b  = bh >> 4;
        const int h  = bh & (HH - 1);
        const int m0 = (tt & 15) * 128;

        const float* qbase = q + ((long)bh * LL + m0) * HD;
        const float* kbase = k + (long)bh * LL * HD;
        const float* vbase = v + (long)bh * LL * HD;

        __syncthreads();

        for (int i = tid; i < 128 * 16; i += 256) {
            const int r = i >> 4, c4 = (i & 15) * 4;
            *reinterpret_cast<float4*>(&sQ[r * F3_QSTR + c4]) =
                *reinterpret_cast<const float4*>(&qbase[(long)r * HD + c4]);
        }

        {
            float* dK = sm + F3_SQSZ;
            float* dV = dK + F3_KSZ;
#pragma unroll
            for (int c = 0; c < 4; c++) {
                const int col = fc0 + c * 16;
                CP_ASYNC16(smem_u32(&dK[frow * F3_KSTR + col]),
                           &kbase[(long)frow * HD + col]);
                CP_ASYNC16(smem_u32(&dV[frow * F3_VSTR + col]),
                           &vbase[(long)frow * HD + col]);
            }
            CP_COMMIT();
        }

        float accO[8][4];
#pragma unroll
        for (int j = 0; j < 8; j++)
#pragma unroll
            for (int c = 0; c < 4; c++) accO[j][c] = 0.f;
        float mrow0 = -1e30f, mrow1 = -1e30f, lrow0 = 0.f, lrow1 = 0.f;

        for (int it = 0; it < 32; it++) {
            CP_WAIT0();
            __syncthreads();

            if (it + 1 < 32) {
                const int j0n = (it + 1) * 64;
                float* dK = sm + F3_SQSZ + ((it + 1) & 1) * F3_KVSZ;
                float* dV = dK + F3_KSZ;
#pragma unroll
                for (int c = 0; c < 4; c++) {
                    const int col = fc0 + c * 16;
                    CP_ASYNC16(smem_u32(&dK[frow * F3_KSTR + col]),
                               &kbase[(long)(j0n + frow) * HD + col]);
                    CP_ASYNC16(smem_u32(&dV[frow * F3_VSTR + col]),
                               &vbase[(long)(j0n + frow) * HD + col]);
                }
            }
            CP_COMMIT();

            const float* sK = sm + F3_SQSZ + (it & 1) * F3_KVSZ;
            const float* sV = sK + F3_KSZ;

            float s[8][4];
#pragma unroll
            for (int j = 0; j < 8; j++)
#pragma unroll
                for (int c = 0; c < 4; c++) s[j][c] = 0.f;
#pragma unroll
            for (int ks = 0; ks < 8; ks++) {
                const int r0 = qrow + ks * 8 + tg;
                const uint32_t a0 = __float_as_uint(sQ[r0]);
                const uint32_t a1 = __float_as_uint(sQ[r0 + 8 * F3_QSTR]);
                const uint32_t a2 = __float_as_uint(sQ[r0 + 4]);
                const uint32_t a3 = __float_as_uint(sQ[r0 + 8 * F3_QSTR + 4]);
#pragma unroll
                for (int j = 0; j < 8; j++) {
                    const int c0 = (j * 8 + g) * F3_KSTR + ks * 8 + tg;
                    mma_tf32(s[j], a0, a1, a2, a3,
                             __float_as_uint(sK[c0]),
                             __float_as_uint(sK[c0 + 4]));
                }
            }

            float mx0 = -1e30f, mx1 = -1e30f;
#pragma unroll
            for (int j = 0; j < 8; j++) {
                mx0 = fmaxf(mx0, fmaxf(s[j][0], s[j][1]));
                mx1 = fmaxf(mx1, fmaxf(s[j][2], s[j][3]));
            }
            mx0 = fmaxf(mx0, __shfl_xor_sync(~0u, mx0, 1));
            mx0 = fmaxf(mx0, __shfl_xor_sync(~0u, mx0, 2));
            mx1 = fmaxf(mx1, __shfl_xor_sync(~0u, mx1, 1));
            mx1 = fmaxf(mx1, __shfl_xor_sync(~0u, mx1, 2));

            const float mn0 = fmaxf(mrow0, mx0);
            const float mn1 = fmaxf(mrow1, mx1);
            const float al0 = __expf(mrow0 - mn0);
            const float al1 = __expf(mrow1 - mn1);
            mrow0 = mn0; mrow1 = mn1;

            float ps0 = 0.f, ps1 = 0.f;
#pragma unroll
            for (int j = 0; j < 8; j++) {
                s[j][0] = __expf(s[j][0] - mn0);
                s[j][1] = __expf(s[j][1] - mn0);
                s[j][2] = __expf(s[j][2] - mn1);
                s[j][3] = __expf(s[j][3] - mn1);
                ps0 += s[j][0] + s[j][1];
                ps1 += s[j][2] + s[j][3];
            }
            ps0 += __shfl_xor_sync(~0u, ps0, 1);
            ps0 += __shfl_xor_sync(~0u, ps0, 2);
            ps1 += __shfl_xor_sync(~0u, ps1, 1);
            ps1 += __shfl_xor_sync(~0u, ps1, 2);
            lrow0 = lrow0 * al0 + ps0;
            lrow1 = lrow1 * al1 + ps1;

#pragma unroll
            for (int j = 0; j < 8; j++) {
                accO[j][0] *= al0; accO[j][1] *= al0;
                accO[j][2] *= al1; accO[j][3] *= al1;
            }

#pragma unroll
            for (int j = 0; j < 8; j++) {
                s[j][0] = to_tf32(s[j][0]);
                s[j][1] = to_tf32(s[j][1]);
                s[j][2] = to_tf32(s[j][2]);
                s[j][3] = to_tf32(s[j][3]);
            }

#pragma unroll
            for (int ks = 0; ks < 8; ks++) {
                const float p0A = __shfl_sync(~0u, s[ks][0], srcA);
                const float p1A = __shfl_sync(~0u, s[ks][1], srcA);
                const float p2A = __shfl_sync(~0u, s[ks][2], srcA);
                const float p3A = __shfl_sync(~0u, s[ks][3], srcA);
                const float p0B = __shfl_sync(~0u, s[ks][0], srcB);
                const float p1B = __shfl_sync(~0u, s[ks][1], srcB);
                const float p2B = __shfl_sync(~0u, s[ks][2], srcB);
                const float p3B = __shfl_sync(~0u, s[ks][3], srcB);
                const uint32_t a0 = __float_as_uint(esel ? p1A : p0A);
                const uint32_t a1 = __float_as_uint(esel ? p3A : p2A);
                const uint32_t a2 = __float_as_uint(esel ? p1B : p0B);
                const uint32_t a3 = __float_as_uint(esel ? p3B : p2B);
#pragma unroll
                for (int j = 0; j < 8; j++) {
                    const int c0 = (ks * 8 + tg) * F3_VSTR + j * 8 + g;
                    mma_tf32(accO[j], a0, a1, a2, a3,
                             __float_as_uint(sV[c0]),
                             __float_as_uint(sV[c0 + 4 * F3_VSTR]));
                }
            }
        }

        const float inv0 = 1.f / lrow0;
        const float inv1 = 1.f / lrow1;
        float* obase = att + ((long)(b * LL + m0 + warp * 16 + g)) * DD + h * HD;
#pragma unroll
        for (int j = 0; j < 8; j++) {
            const int c = j * 8 + tg * 2;
            *reinterpret_cast<float2*>(&obase[c]) =
                make_float2(to_tf32(accO[j][0] * inv0), to_tf32(accO[j][1] * inv0));
            *reinterpret_cast<float2*>(&obase[(long)8 * DD + c]) =
                make_float2(to_tf32(accO[j][2] * inv1), to_tf32(accO[j][3] * inv1));
        }
    }
}

// ---------------------------------------------------------------------------
// RMSNorm
// ---------------------------------------------------------------------------
__global__ void rmsnorm_kernel(const float* __restrict__ x,
                               const float* __restrict__ scale,
                               float* __restrict__ out)
{
    const int row = blockIdx.x;
    const float4 a = *((const float4*)(x + (long)row * DD) + threadIdx.x);
    float ss = a.x * a.x + a.y * a.y + a.z * a.z + a.w * a.w;

    __shared__ float red[8];
    for (int o = 16; o > 0; o >>= 1) ss += __shfl_xor_sync(~0u, ss, o);
    if ((threadIdx.x & 31) == 0) red[threadIdx.x >> 5] = ss;
    __syncthreads();
    __shared__ float rinv;
    if (threadIdx.x == 0) {
        float t = 0.f;
#pragma unroll
        for (int i = 0; i < 8; i++) t += red[i];
        rinv = rsqrtf(t * (1.0f / DD) + EPS);
    }
    __syncthreads();

    const float4 sc = *((const float4*)scale + threadIdx.x);
    float4 o4;
    o4.x = a.x * rinv * sc.x; o4.y = a.y * rinv * sc.y;
    o4.z = a.z * rinv * sc.z; o4.w = a.w * rinv * sc.w;
    *((float4*)(out + (long)row * DD) + threadIdx.x) = o4;
}

// ---------------------------------------------------------------------------
// AdaLN modulation — planar cp, vectorized; emits tf32-rounded xm
// ---------------------------------------------------------------------------
__global__ void modulate_kernel(const float* __restrict__ xn,
                                const float* __restrict__ cp,
                                float* __restrict__ xm)
{
    const int i = blockIdx.x * blockDim.x + threadIdx.x;
    const int row = i / (DD / 4);
    const int d4 = (i % (DD / 4)) * 4;
    const long base = (long)row * 3 * DD + d4;
    const float4 a  = *reinterpret_cast<const float4*>(&xn[(long)row * DD + d4]);
    const float4 sc = *reinterpret_cast<const float4*>(&cp[base]);
    const float4 sh = *reinterpret_cast<const float4*>(&cp[base + DD]);
    float4 o;
    o.x = to_tf32(a.x * (1.f + sc.x) + sh.x);
    o.y = to_tf32(a.y * (1.f + sc.y) + sh.y);
    o.z = to_tf32(a.z * (1.f + sc.z) + sh.z);
    o.w = to_tf32(a.w * (1.f + sc.w) + sh.w);
    *reinterpret_cast<float4*>(&xm[(long)row * DD + d4]) = o;
}

// ---------------------------------------------------------------------------
// RoPE + head scatter — all outputs [B,H,L,HD], coalesced, tf32-rounded
// ---------------------------------------------------------------------------
__global__ void rope_kernel(const float* __restrict__ qkv,
                            const float* __restrict__ pos,
                            float* __restrict__ q,
                            float* __restrict__ k,
                            float* __restrict__ v)
{
    const int bl = blockIdx.x;
    const int b = bl >> 11;
    const int l = bl & (LL - 1);
    __shared__ float srow[3 * DD];
    __shared__ float spos[2 * HD];

    const float4* src = (const float4*)(qkv + (long)bl * (3 * DD));
    for (int i = threadIdx.x; i < (3 * DD) / 4; i += blockDim.x)
        ((float4*)srow)[i] = src[i];
    if (threadIdx.x < (2 * HD) / 4)
        ((float4*)spos)[threadIdx.x] =
            ((const float4*)(pos + (long)bl * (2 * HD)))[threadIdx.x];
    __syncthreads();

    for (int idx = threadIdx.x; idx < DD; idx += blockDim.x) {
        const int h = idx >> 6;
        const int d = idx & (HD - 1);
        const int c = (d * HH + h) * 3;
        const int dp = (d < HD / 2) ? d + HD / 2 : d - HD / 2;
        const int c2 = (dp * HH + h) * 3;
        const float sgn = (d < HD / 2) ? -1.f : 1.f;
        const float s = spos[2 * d];
        const float ct = spos[2 * d + 1];

        const float qo = srow[c] * ct + sgn * srow[c2] * s;
        const float ko = srow[c + 1] * ct + sgn * srow[c2 + 1] * s;

        const long o = ((long)(b * HH + h) * LL + l) * HD + d;
        q[o] = to_tf32(qo * 0.125f);
        k[o] = to_tf32(ko);
        v[o] = to_tf32(srow[c + 2]);
    }
}

// ---------------------------------------------------------------------------
// Launch
// ---------------------------------------------------------------------------
extern "C" void kernel_launch(void* const* d_in, const int* in_sizes, int n_in,
                              void* d_out, int out_size)
{
    const float* x         = (const float*)d_in[0];
    const float* cond      = (const float*)d_in[1];
    const float* pos       = (const float*)d_in[2];
    const float* rms_scale = (const float*)d_in[3];
    const float* W_cond    = (const float*)d_in[4];
    const float* W_qkv     = (const float*)d_in[5];
    const float* W_out     = (const float*)d_in[6];
    float* out = (float*)d_out;

    float *xn, *cp, *xm, *qkv, *q, *k, *v, *att, *cr, *wc, *wq, *wo;
    cudaGetSymbolAddress((void**)&xn,  g_xn);
    cudaGetSymbolAddress((void**)&cp,  g_cp);
    cudaGetSymbolAddress((void**)&xm,  g_xm);
    cudaGetSymbolAddress((void**)&qkv, g_qkv);
    cudaGetSymbolAddress((void**)&q,   g_q);
    cudaGetSymbolAddress((void**)&k,   g_k);
    cudaGetSymbolAddress((void**)&v,   g_v);
    cudaGetSymbolAddress((void**)&att, g_att);
    cudaGetSymbolAddress((void**)&cr,  g_cr);
    cudaGetSymbolAddress((void**)&wc,  g_wc);
    cudaGetSymbolAddress((void**)&wq,  g_wq);
    cudaGetSymbolAddress((void**)&wo,  g_wo);

    static bool attr_set = false;
    if (!attr_set) {
        cudaFuncSetAttribute(flash_kernel,
                             cudaFuncAttributeMaxDynamicSharedMemorySize,
                             F3_TOT * sizeof(float));
        cudaFuncSetAttribute(mma_gemm<128, 128, false>,
                             cudaFuncAttributeMaxDynamicSharedMemorySize,
                             MMA_SMEM_BYTES);
        cudaFuncSetAttribute(mma_gemm<128, 128, true>,
                             cudaFuncAttributeMaxDynamicSharedMemorySize,
                             MMA_SMEM_BYTES);
        attr_set = true;
    }

    // 0. fused tf32 pre-round (cond + weights; W_cond columns planar-permuted)
    round_all<<<(int)(R_C3 / 256), 256>>>(cond, W_cond, W_qkv, W_out,
                                          cr, wc, wq, wo);

    // 1. RMSNorm
    rmsnorm_kernel<<<BL, 256>>>(x, rms_scale, xn);

    // 2. cond projection (-> planar cp)
    mma_gemm<128, 128, false><<<dim3(24, 32, 1), 256, MMA_SMEM_BYTES>>>(
        cr, wc, cp, DD, DD, 3 * DD, 3 * DD,
        0, 0, 1, 0, 0, nullptr, nullptr);

    // 3. modulate
    modulate_kernel<<<(BL * DD / 4) / 256, 256>>>(xn, cp, xm);

    // 4. qkv projection
    mma_gemm<128, 128, false><<<dim3(24, 32, 1), 256, MMA_SMEM_BYTES>>>(
        xm, wq, qkv, DD, DD, 3 * DD, 3 * DD,
        0, 0, 1, 0, 0, nullptr, nullptr);

    // 5. RoPE + head scatter
    rope_kernel<<<BL, 256>>>(qkv, pos, q, k, v);

    // 6-8. flash attention v4 (persistent, one wave) -> att [B,L,D]
    flash_kernel<<<256, 256, F3_TOT * sizeof(float)>>>(q, k, v, att);

    // 9. out projection + residual + gate (planar gate)
    mma_gemm<128, 128, true><<<dim3(8, 32, 1), 256, MMA_SMEM_BYTES>>>(
        att, wo, out, DD, DD, DD, DD,
        0, 0, 1, 0, 0, x, cp);
}